// round 12
// baseline (speedup 1.0000x reference)
#include <cuda_runtime.h>
#include <cuda_bf16.h>
#include <cstdint>

#define NN 131072      // B*L nodes
#define LL 2048        // nodes per tree
#define HH 128         // hidden
#define LOG2L 11
#define GEMM_GRID 296  // 2 CTAs per SM x 148 SMs, persistent
#define NTILES 2048    // NN / 64
#define FTILES 1024    // NN / 128 (fused kernel, 128-row tiles)
#define FGRID 148

// ---------------- scratch (device globals; no allocation allowed) ----------
__device__ float g_bufA[NN * HH];   // x_up
__device__ float g_bufB[NN * HH];   // layer cur / dotv buffer
__device__ float g_bufC[NN * HH];   // gemm out
__device__ float g_bufD[NN * HH];   // fused chain ping-pong
__device__ float g_pre[16];         // [0..11] w_e per up layer, [12]=W0·a_s, [13]=W0·a_d
__device__ __nv_bfloat16 g_wt[12 * 16384];  // 6 mats x {hi,lo} planes, transposed [n][k]

__device__ __forceinline__ float lrelu(float v) { return v > 0.f ? v : 0.2f * v; }
__device__ __forceinline__ float warpsum(float v) {
    #pragma unroll
    for (int o = 16; o; o >>= 1) v += __shfl_xor_sync(0xffffffffu, v, o);
    return v;
}
__device__ __forceinline__ float dot4(float4 a, float4 b) {
    return a.x * b.x + a.y * b.y + a.z * b.z + a.w * b.w;
}
__device__ __forceinline__ uint32_t smem_u32(const void* p) {
    uint32_t a;
    asm("{ .reg .u64 t; cvta.to.shared.u64 t, %1; cvt.u32.u64 %0, t; }" : "=r"(a) : "l"(p));
    return a;
}

// ======================= HMMA helpers (sm_80+ PTX) =========================
__device__ __forceinline__ void ldsm_x4(uint32_t* r, uint32_t addr) {
    asm volatile("ldmatrix.sync.aligned.m8n8.x4.shared.b16 {%0,%1,%2,%3}, [%4];"
                 : "=r"(r[0]), "=r"(r[1]), "=r"(r[2]), "=r"(r[3]) : "r"(addr));
}
__device__ __forceinline__ void mma16816(float* c, const uint32_t* a, const uint32_t* b) {
    asm volatile("mma.sync.aligned.m16n8k16.row.col.f32.bf16.bf16.f32 "
                 "{%0,%1,%2,%3}, {%4,%5,%6,%7}, {%8,%9}, {%0,%1,%2,%3};"
                 : "+f"(c[0]), "+f"(c[1]), "+f"(c[2]), "+f"(c[3])
                 : "r"(a[0]), "r"(a[1]), "r"(a[2]), "r"(a[3]), "r"(b[0]), "r"(b[1]));
}

// SMEM layout, plain GEMM (row stride 272 B)
#define A_HI 0
#define A_LO 17408
#define B_HI 34816
#define B_LO 69632
#define SMEM_GEMM 104448
// SMEM layout, fused kernel (128-row A, two B matrices)
#define FA_HI 0
#define FA_LO 34816
#define FB1_HI 69632
#define FB1_LO 104448
#define FB2_HI 139264
#define FB2_LO 174080
#define SMEM_FUSED 208896

// ---------------- weight pre-conversion: W[k][n] -> hi/lo bf16 [n][k] ------
__global__ void wconv_k(const float* __restrict__ up_W,
                        const float* __restrict__ down_W,
                        const float* __restrict__ lin_W) {
    int bx = blockIdx.x;
    int mat = bx >> 7, n = bx & 127, k = threadIdx.x;
    const float* W = (mat < 2) ? up_W + mat * 16384
                   : (mat < 4) ? down_W + (mat - 2) * 16384
                               : lin_W + (mat - 4) * 16384;
    float w = W[k * 128 + n];
    __nv_bfloat16 hb = __float2bfloat16(w);
    float hf = __bfloat162float(hb);
    g_wt[(mat * 2 + 0) * 16384 + n * 128 + k] = hb;
    g_wt[(mat * 2 + 1) * 16384 + n * 128 + k] = __float2bfloat16(w - hf);
}

// ============== persistent HMMA GEMM: C = f(A) @ W, W loaded ONCE ==========
// If x0 != nullptr: A row v = relu(up0_attn(x0; v) * W0col + ub)  (scalar GAT,
// all-lane-broadcast math, no reductions — safe at low occupancy).
__global__ void __launch_bounds__(256, 2)
gemm_hmma(const float* __restrict__ A,
          const float* __restrict__ x0, const float* __restrict__ W0,
          const float* __restrict__ ub, const float* __restrict__ edge_attr,
          const __nv_bfloat16* __restrict__ Wt,
          float* __restrict__ C) {
    extern __shared__ char smem[];
    uint32_t sb = smem_u32(smem);
    int tid = threadIdx.x;

    const uint4* Bh = (const uint4*)Wt;
    const uint4* Bl = (const uint4*)(Wt + 16384);
    #pragma unroll
    for (int i = tid; i < 2048; i += 256) {
        int n = i >> 4, kq = i & 15;
        uint32_t off = n * 272 + kq * 16;
        *(uint4*)(smem + B_HI + off) = Bh[i];
        *(uint4*)(smem + B_LO + off) = Bl[i];
    }

    int wid = tid >> 5, lane = tid & 31;
    int m0 = (wid & 1) * 32, n0 = (wid >> 1) * 32;
    int g = lane >> 3, r = lane & 7;
    uint32_t aoff0 = (uint32_t)((m0 + (g & 1) * 8 + r) * 272 + (g >> 1) * 16);
    uint32_t boff0 = (uint32_t)((n0 + (g >> 1) * 8 + r) * 272 + (g & 1) * 16);
    int cr = lane >> 2, cc = (lane & 3) * 2;

    for (int tile = blockIdx.x; tile < NTILES; tile += GEMM_GRID) {
        #pragma unroll 1
        for (int i = tid; i < 2048; i += 256) {
            int row = i >> 5, c4 = i & 31;
            float4 v;
            if (x0) {
                // fused layer-0 scalar GAT (broadcast loads, no reductions)
                int vv = tile * 64 + row;
                int l = vv & (LL - 1), bi = vv >> LOG2L;
                float xv = x0[vv];
                int nc = (l < 1023) ? 2 : ((l == 1023) ? 1 : 0);
                float comb;
                if (nc == 0) {
                    comb = xv;
                } else {
                    float was = g_pre[12], wad = g_pre[13];
                    int c1 = vv + l + 1;
                    float x1 = x0[c1];
                    float x2 = (nc == 2) ? x0[c1 + 1] : 0.f;
                    long e1 = (long)bi * 2047 + 2 * l;
                    const float* ea1 = edge_attr + e1 * 4;
                    float e1s = ea1[0] * g_pre[0] + ea1[1] * g_pre[1] +
                                ea1[2] * g_pre[2] + ea1[3] * g_pre[3];
                    float e2s = 0.f;
                    if (nc == 2) {
                        const float* ea2 = ea1 + 4;
                        e2s = ea2[0] * g_pre[0] + ea2[1] * g_pre[1] +
                              ea2[2] * g_pre[2] + ea2[3] * g_pre[3];
                    }
                    float adv = xv * wad;
                    float s1 = lrelu(x1 * was + adv + e1s);
                    float s2 = (nc == 2) ? lrelu(x2 * was + adv + e2s) : -1e30f;
                    float emean = (nc == 2) ? 0.5f * (e1s + e2s) : e1s;
                    float ss = lrelu(xv * was + adv + emean);
                    float m = fmaxf(ss, fmaxf(s1, s2));
                    float w1 = __expf(s1 - m);
                    float w2 = (nc == 2) ? __expf(s2 - m) : 0.f;
                    float ws = __expf(ss - m);
                    comb = (w1 * x1 + w2 * x2 + ws * xv) / (w1 + w2 + ws);
                }
                float4 w04 = ((const float4*)W0)[c4];
                float4 b4 = ((const float4*)ub)[c4];
                v.x = fmaxf(comb * w04.x + b4.x, 0.f);
                v.y = fmaxf(comb * w04.y + b4.y, 0.f);
                v.z = fmaxf(comb * w04.z + b4.z, 0.f);
                v.w = fmaxf(comb * w04.w + b4.w, 0.f);
            } else {
                v = ((const float4*)(A + (size_t)tile * 64 * 128))[i];
            }
            float f[4] = {v.x, v.y, v.z, v.w};
            union { uint2 u; __nv_bfloat16 h[4]; } ph, pl;
            #pragma unroll
            for (int e = 0; e < 4; e++) {
                __nv_bfloat16 hb = __float2bfloat16(f[e]);
                ph.h[e] = hb;
                pl.h[e] = __float2bfloat16(f[e] - __bfloat162float(hb));
            }
            uint32_t off = row * 272 + c4 * 8;
            *(uint2*)(smem + A_HI + off) = ph.u;
            *(uint2*)(smem + A_LO + off) = pl.u;
        }
        __syncthreads();

        float acc[2][4][4];
        #pragma unroll
        for (int a = 0; a < 2; a++)
            #pragma unroll
            for (int b = 0; b < 4; b++)
                #pragma unroll
                for (int c = 0; c < 4; c++) acc[a][b][c] = 0.f;

        #pragma unroll 4
        for (int k16 = 0; k16 < 8; k16++) {
            uint32_t ah[2][4], al[2][4], bh[4][2];
            ldsm_x4(ah[0], sb + A_HI + aoff0 + k16 * 32);
            ldsm_x4(ah[1], sb + A_HI + aoff0 + 16 * 272 + k16 * 32);
            ldsm_x4(al[0], sb + A_LO + aoff0 + k16 * 32);
            ldsm_x4(al[1], sb + A_LO + aoff0 + 16 * 272 + k16 * 32);
            ldsm_x4(&bh[0][0], sb + B_HI + boff0 + k16 * 32);
            ldsm_x4(&bh[2][0], sb + B_HI + boff0 + 16 * 272 + k16 * 32);
            #pragma unroll
            for (int mf = 0; mf < 2; mf++)
                #pragma unroll
                for (int nf = 0; nf < 4; nf++)
                    mma16816(acc[mf][nf], ah[mf], bh[nf]);
            #pragma unroll
            for (int mf = 0; mf < 2; mf++)
                #pragma unroll
                for (int nf = 0; nf < 4; nf++)
                    mma16816(acc[mf][nf], al[mf], bh[nf]);
        }
        #pragma unroll 4
        for (int k16 = 0; k16 < 8; k16++) {
            uint32_t ah[2][4], bl[4][2];
            ldsm_x4(ah[0], sb + A_HI + aoff0 + k16 * 32);
            ldsm_x4(ah[1], sb + A_HI + aoff0 + 16 * 272 + k16 * 32);
            ldsm_x4(&bl[0][0], sb + B_LO + boff0 + k16 * 32);
            ldsm_x4(&bl[2][0], sb + B_LO + boff0 + 16 * 272 + k16 * 32);
            #pragma unroll
            for (int mf = 0; mf < 2; mf++)
                #pragma unroll
                for (int nf = 0; nf < 4; nf++)
                    mma16816(acc[mf][nf], ah[mf], bl[nf]);
        }

        size_t rbase = (size_t)tile * 64;
        #pragma unroll
        for (int mf = 0; mf < 2; mf++) {
            #pragma unroll
            for (int nf = 0; nf < 4; nf++) {
                int col = n0 + nf * 8 + cc;
                int row0 = m0 + mf * 16 + cr;
                *(float2*)(C + (rbase + row0) * 128 + col) =
                    make_float2(acc[mf][nf][0], acc[mf][nf][1]);
                *(float2*)(C + (rbase + row0 + 8) * 128 + col) =
                    make_float2(acc[mf][nf][2], acc[mf][nf][3]);
            }
        }
        __syncthreads();
    }
}

// ====== fused lin+down chain: out = relu(gather(gC)+xup chain) @W1 relu @W2 =
__global__ void __launch_bounds__(512, 1)
gemm_fused2(const float* __restrict__ gC, const float* __restrict__ xup,
            const float* __restrict__ dbias,
            const __nv_bfloat16* __restrict__ Wt1, const float* __restrict__ lbias,
            const __nv_bfloat16* __restrict__ Wt2,
            float* __restrict__ out) {
    extern __shared__ char smem[];
    uint32_t sb = smem_u32(smem);
    int tid = threadIdx.x;

    {
        const uint4* B1h = (const uint4*)Wt1;
        const uint4* B1l = (const uint4*)(Wt1 + 16384);
        const uint4* B2h = (const uint4*)Wt2;
        const uint4* B2l = (const uint4*)(Wt2 + 16384);
        #pragma unroll
        for (int i = tid; i < 2048; i += 512) {
            int n = i >> 4, kq = i & 15;
            uint32_t off = n * 272 + kq * 16;
            *(uint4*)(smem + FB1_HI + off) = B1h[i];
            *(uint4*)(smem + FB1_LO + off) = B1l[i];
            *(uint4*)(smem + FB2_HI + off) = B2h[i];
            *(uint4*)(smem + FB2_LO + off) = B2l[i];
        }
    }

    int wid = tid >> 5, lane = tid & 31;
    int m0 = (wid & 3) * 32, n0 = (wid >> 2) * 32;
    int g = lane >> 3, r = lane & 7;
    uint32_t aoff0 = (uint32_t)((m0 + (g & 1) * 8 + r) * 272 + (g >> 1) * 16);
    uint32_t boff0 = (uint32_t)((n0 + (g >> 1) * 8 + r) * 272 + (g & 1) * 16);
    int cr = lane >> 2, cc = (lane & 3) * 2;

    for (int tile = blockIdx.x; tile < FTILES; tile += FGRID) {
        #pragma unroll
        for (int i = tid; i < 4096; i += 512) {
            int row = i >> 5, c4 = i & 31;
            int vv = tile * 128 + row;
            int l = vv & (LL - 1);
            float4 b4 = ((const float4*)dbias)[c4];
            float4 xu = ((const float4*)xup)[(size_t)vv * 32 + c4];
            float4 v;
            if (l == 0) {
                v.x = fmaxf(b4.x, 0.f) + xu.x;
                v.y = fmaxf(b4.y, 0.f) + xu.y;
                v.z = fmaxf(b4.z, 0.f) + xu.z;
                v.w = fmaxf(b4.w, 0.f) + xu.w;
            } else {
                int p = vv - l + ((l - 1) >> 1);
                float4 cp = ((const float4*)gC)[(size_t)p * 32 + c4];
                v.x = fmaxf(cp.x + b4.x, 0.f) + xu.x;
                v.y = fmaxf(cp.y + b4.y, 0.f) + xu.y;
                v.z = fmaxf(cp.z + b4.z, 0.f) + xu.z;
                v.w = fmaxf(cp.w + b4.w, 0.f) + xu.w;
            }
            float f[4] = {v.x, v.y, v.z, v.w};
            union { uint2 u; __nv_bfloat16 h[4]; } ph, pl;
            #pragma unroll
            for (int e = 0; e < 4; e++) {
                __nv_bfloat16 hb = __float2bfloat16(f[e]);
                ph.h[e] = hb;
                pl.h[e] = __float2bfloat16(f[e] - __bfloat162float(hb));
            }
            uint32_t off = row * 272 + c4 * 8;
            *(uint2*)(smem + FA_HI + off) = ph.u;
            *(uint2*)(smem + FA_LO + off) = pl.u;
        }
        __syncthreads();

        float acc[2][4][4];
        #pragma unroll
        for (int a = 0; a < 2; a++)
            #pragma unroll
            for (int b = 0; b < 4; b++)
                #pragma unroll
                for (int c = 0; c < 4; c++) acc[a][b][c] = 0.f;

        #pragma unroll 4
        for (int k16 = 0; k16 < 8; k16++) {
            uint32_t ah[2][4], al[2][4], bh[4][2];
            ldsm_x4(ah[0], sb + FA_HI + aoff0 + k16 * 32);
            ldsm_x4(ah[1], sb + FA_HI + aoff0 + 16 * 272 + k16 * 32);
            ldsm_x4(al[0], sb + FA_LO + aoff0 + k16 * 32);
            ldsm_x4(al[1], sb + FA_LO + aoff0 + 16 * 272 + k16 * 32);
            ldsm_x4(&bh[0][0], sb + FB1_HI + boff0 + k16 * 32);
            ldsm_x4(&bh[2][0], sb + FB1_HI + boff0 + 16 * 272 + k16 * 32);
            #pragma unroll
            for (int mf = 0; mf < 2; mf++)
                #pragma unroll
                for (int nf = 0; nf < 4; nf++)
                    mma16816(acc[mf][nf], ah[mf], bh[nf]);
            #pragma unroll
            for (int mf = 0; mf < 2; mf++)
                #pragma unroll
                for (int nf = 0; nf < 4; nf++)
                    mma16816(acc[mf][nf], al[mf], bh[nf]);
        }
        #pragma unroll 4
        for (int k16 = 0; k16 < 8; k16++) {
            uint32_t ah[2][4], bl[4][2];
            ldsm_x4(ah[0], sb + FA_HI + aoff0 + k16 * 32);
            ldsm_x4(ah[1], sb + FA_HI + aoff0 + 16 * 272 + k16 * 32);
            ldsm_x4(&bl[0][0], sb + FB1_LO + boff0 + k16 * 32);
            ldsm_x4(&bl[2][0], sb + FB1_LO + boff0 + 16 * 272 + k16 * 32);
            #pragma unroll
            for (int mf = 0; mf < 2; mf++)
                #pragma unroll
                for (int nf = 0; nf < 4; nf++)
                    mma16816(acc[mf][nf], ah[mf], bl[nf]);
        }
        __syncthreads();

        #pragma unroll
        for (int mf = 0; mf < 2; mf++) {
            #pragma unroll
            for (int nf = 0; nf < 4; nf++) {
                int col = n0 + nf * 8 + cc;
                float bx = lbias[col], by = lbias[col + 1];
                #pragma unroll
                for (int j = 0; j < 2; j++) {
                    int row = m0 + mf * 16 + cr + j * 8;
                    float f0 = fmaxf(acc[mf][nf][2 * j + 0] + bx, 0.f);
                    float f1 = fmaxf(acc[mf][nf][2 * j + 1] + by, 0.f);
                    union { uint32_t u; __nv_bfloat16 h[2]; } uh, ul;
                    uh.h[0] = __float2bfloat16(f0);
                    uh.h[1] = __float2bfloat16(f1);
                    ul.h[0] = __float2bfloat16(f0 - __bfloat162float(uh.h[0]));
                    ul.h[1] = __float2bfloat16(f1 - __bfloat162float(uh.h[1]));
                    uint32_t off = row * 272 + col * 2;
                    *(uint32_t*)(smem + FA_HI + off) = uh.u;
                    *(uint32_t*)(smem + FA_LO + off) = ul.u;
                }
            }
        }
        __syncthreads();

        #pragma unroll
        for (int a = 0; a < 2; a++)
            #pragma unroll
            for (int b = 0; b < 4; b++)
                #pragma unroll
                for (int c = 0; c < 4; c++) acc[a][b][c] = 0.f;

        #pragma unroll 4
        for (int k16 = 0; k16 < 8; k16++) {
            uint32_t ah[2][4], al[2][4], bh[4][2];
            ldsm_x4(ah[0], sb + FA_HI + aoff0 + k16 * 32);
            ldsm_x4(ah[1], sb + FA_HI + aoff0 + 16 * 272 + k16 * 32);
            ldsm_x4(al[0], sb + FA_LO + aoff0 + k16 * 32);
            ldsm_x4(al[1], sb + FA_LO + aoff0 + 16 * 272 + k16 * 32);
            ldsm_x4(&bh[0][0], sb + FB2_HI + boff0 + k16 * 32);
            ldsm_x4(&bh[2][0], sb + FB2_HI + boff0 + 16 * 272 + k16 * 32);
            #pragma unroll
            for (int mf = 0; mf < 2; mf++)
                #pragma unroll
                for (int nf = 0; nf < 4; nf++)
                    mma16816(acc[mf][nf], ah[mf], bh[nf]);
            #pragma unroll
            for (int mf = 0; mf < 2; mf++)
                #pragma unroll
                for (int nf = 0; nf < 4; nf++)
                    mma16816(acc[mf][nf], al[mf], bh[nf]);
        }
        #pragma unroll 4
        for (int k16 = 0; k16 < 8; k16++) {
            uint32_t ah[2][4], bl[4][2];
            ldsm_x4(ah[0], sb + FA_HI + aoff0 + k16 * 32);
            ldsm_x4(ah[1], sb + FA_HI + aoff0 + 16 * 272 + k16 * 32);
            ldsm_x4(&bl[0][0], sb + FB2_LO + boff0 + k16 * 32);
            ldsm_x4(&bl[2][0], sb + FB2_LO + boff0 + 16 * 272 + k16 * 32);
            #pragma unroll
            for (int mf = 0; mf < 2; mf++)
                #pragma unroll
                for (int nf = 0; nf < 4; nf++)
                    mma16816(acc[mf][nf], ah[mf], bl[nf]);
        }

        size_t rbase = (size_t)tile * 128;
        #pragma unroll
        for (int mf = 0; mf < 2; mf++) {
            #pragma unroll
            for (int nf = 0; nf < 4; nf++) {
                int col = n0 + nf * 8 + cc;
                int row0 = m0 + mf * 16 + cr;
                *(float2*)(out + (rbase + row0) * 128 + col) =
                    make_float2(acc[mf][nf][0], acc[mf][nf][1]);
                *(float2*)(out + (rbase + row0 + 8) * 128 + col) =
                    make_float2(acc[mf][nf][2], acc[mf][nf][3]);
            }
        }
        __syncthreads();
    }
}

// ---------------- tiny precompute: w_e = We @ a_e per up layer, W0 dots ----
__global__ void precompute_k(const float* __restrict__ up_We,
                             const float* __restrict__ up_ae,
                             const float* __restrict__ up_W0,
                             const float* __restrict__ as0,
                             const float* __restrict__ ad0) {
    int lane = threadIdx.x;
    for (int i = 0; i < 3; i++) {
        for (int d = 0; d < 4; d++) {
            float s = 0.f;
            for (int t = lane; t < HH; t += 32)
                s += up_We[(i * 4 + d) * HH + t] * up_ae[i * HH + t];
            s = warpsum(s);
            if (lane == 0) g_pre[i * 4 + d] = s;
        }
    }
    float s = 0.f;
    for (int t = lane; t < HH; t += 32) s += up_W0[t] * as0[t];
    s = warpsum(s);
    if (lane == 0) g_pre[12] = s;
    s = 0.f;
    for (int t = lane; t < HH; t += 32) s += up_W0[t] * ad0[t];
    s = warpsum(s);
    if (lane == 0) g_pre[13] = s;
}

// ---------------- up attention (standalone): warp per node -----------------
__global__ void up_attn_k(const float* __restrict__ h, const float* __restrict__ a_s,
                          const float* __restrict__ a_d,
                          const float* __restrict__ edge_attr, int layer,
                          const float* __restrict__ bias, float* __restrict__ out) {
    int w = threadIdx.x >> 5, lane = threadIdx.x & 31;
    int v = blockIdx.x * 8 + w;
    int l = v & (LL - 1), bi = v >> LOG2L;
    const float4* H = (const float4*)h;
    float4 hv = H[(size_t)v * 32 + lane];
    float4 b4 = ((const float4*)bias)[lane];
    int nc = (l < 1023) ? 2 : ((l == 1023) ? 1 : 0);
    float4* O = (float4*)(out + (size_t)v * HH);
    if (nc == 0) {
        float4 o;
        o.x = fmaxf(hv.x + b4.x, 0.f); o.y = fmaxf(hv.y + b4.y, 0.f);
        o.z = fmaxf(hv.z + b4.z, 0.f); o.w = fmaxf(hv.w + b4.w, 0.f);
        O[lane] = o;
        return;
    }
    int c1 = v + l + 1;
    float4 h1 = H[(size_t)c1 * 32 + lane];
    float4 h2 = (nc == 2) ? H[(size_t)(c1 + 1) * 32 + lane] : make_float4(0, 0, 0, 0);
    float4 as4 = ((const float4*)a_s)[lane];
    float4 ad4 = ((const float4*)a_d)[lane];
    float A1 = warpsum(dot4(h1, as4));
    float A2 = warpsum(dot4(h2, as4));
    float AV = warpsum(dot4(hv, as4));
    float DV = warpsum(dot4(hv, ad4));

    const float* we = g_pre + layer * 4;
    long e1 = (long)bi * 2047 + 2 * l;
    const float* ea1 = edge_attr + e1 * 4;
    float e1s = ea1[0] * we[0] + ea1[1] * we[1] + ea1[2] * we[2] + ea1[3] * we[3];
    float e2s = 0.f;
    if (nc == 2) {
        const float* ea2 = ea1 + 4;
        e2s = ea2[0] * we[0] + ea2[1] * we[1] + ea2[2] * we[2] + ea2[3] * we[3];
    }
    float s1 = lrelu(A1 + DV + e1s);
    float s2 = (nc == 2) ? lrelu(A2 + DV + e2s) : -1e30f;
    float emean = (nc == 2) ? 0.5f * (e1s + e2s) : e1s;
    float ss = lrelu(AV + DV + emean);
    float m = fmaxf(ss, fmaxf(s1, s2));
    float w1 = __expf(s1 - m);
    float w2 = (nc == 2) ? __expf(s2 - m) : 0.f;
    float ws = __expf(ss - m);
    float inv = 1.f / (w1 + w2 + ws);
    float4 o;
    o.x = fmaxf((w1 * h1.x + w2 * h2.x + ws * hv.x) * inv + b4.x, 0.f);
    o.y = fmaxf((w1 * h1.y + w2 * h2.y + ws * hv.y) * inv + b4.y, 0.f);
    o.z = fmaxf((w1 * h1.z + w2 * h2.z + ws * hv.z) * inv + b4.z, 0.f);
    o.w = fmaxf((w1 * h1.w + w2 * h2.w + ws * hv.w) * inv + b4.w, 0.f);
    O[lane] = o;
}

// ------- last down_attn fused with final dot: warp per node ---------------
__global__ void down_final_k(const float* __restrict__ h, const float* __restrict__ bias,
                             const float* __restrict__ x_up, const float* __restrict__ wlast,
                             float* __restrict__ emb, float* __restrict__ dotv) {
    int w = threadIdx.x >> 5, lane = threadIdx.x & 31;
    int v = blockIdx.x * 8 + w;
    int l = v & (LL - 1);
    float4 xu = ((const float4*)x_up)[(size_t)v * 32 + lane];
    float4 b4 = ((const float4*)bias)[lane];
    float4 val;
    if (l == 0) val = b4;
    else {
        int p = v - l + ((l - 1) >> 1);
        float4 hp = ((const float4*)h)[(size_t)p * 32 + lane];
        val.x = hp.x + b4.x; val.y = hp.y + b4.y;
        val.z = hp.z + b4.z; val.w = hp.w + b4.w;
    }
    float4 o;
    o.x = fmaxf(val.x, 0.f) + xu.x;
    o.y = fmaxf(val.y, 0.f) + xu.y;
    o.z = fmaxf(val.z, 0.f) + xu.z;
    o.w = fmaxf(val.w, 0.f) + xu.w;
    ((float4*)(emb + (size_t)v * HH))[lane] = o;
    float4 w4 = ((const float4*)wlast)[lane];
    float q = warpsum(dot4(o, w4));
    if (lane == 0) dotv[v] = q;
}

// ---------------- out[v] = dotv[v] - dotv[root(v)] -------------------------
__global__ void sub_k(const float* __restrict__ dotv, float* __restrict__ out) {
    int v = blockIdx.x * 256 + threadIdx.x;
    out[v] = dotv[v] - dotv[v & ~(LL - 1)];
}

// ---------------------------------------------------------------------------
extern "C" void kernel_launch(void* const* d_in, const int* in_sizes, int n_in,
                              void* d_out, int out_size) {
    const float* x         = (const float*)d_in[0];
    const float* edge_attr = (const float*)d_in[3];
    const float* up_W0     = (const float*)d_in[4];
    const float* up_W      = (const float*)d_in[5];
    const float* up_as     = (const float*)d_in[6];
    const float* up_ad     = (const float*)d_in[7];
    const float* up_We     = (const float*)d_in[8];
    const float* up_ae     = (const float*)d_in[9];
    const float* up_b      = (const float*)d_in[10];
    const float* down_W    = (const float*)d_in[11];
    const float* down_b    = (const float*)d_in[16];
    const float* lin_W     = (const float*)d_in[17];
    const float* lin_b     = (const float*)d_in[18];
    const float* lin_lW    = (const float*)d_in[19];

    float *bufA, *bufB, *bufC, *bufD;
    __nv_bfloat16* wt;
    cudaGetSymbolAddress((void**)&bufA, g_bufA);
    cudaGetSymbolAddress((void**)&bufB, g_bufB);
    cudaGetSymbolAddress((void**)&bufC, g_bufC);
    cudaGetSymbolAddress((void**)&bufD, g_bufD);
    cudaGetSymbolAddress((void**)&wt, g_wt);

    cudaFuncSetAttribute(gemm_hmma, cudaFuncAttributeMaxDynamicSharedMemorySize,
                         SMEM_GEMM);
    cudaFuncSetAttribute(gemm_fused2, cudaFuncAttributeMaxDynamicSharedMemorySize,
                         SMEM_FUSED);

    float* out = (float*)d_out;
    float* emb = out + NN;   // output tuple: (out[B*L], emb[B*L*H]) concatenated

    // mats: 0,1 = up_W[0..1]; 2,3 = down_W[0..1]; 4,5 = lin_W[0..1]
    #define WT(m) (wt + (m) * 2 * 16384)
    #define NO0 nullptr, nullptr, nullptr, nullptr

    precompute_k<<<1, 32>>>(up_We, up_ae, up_W0, up_as, up_ad);
    wconv_k<<<768, 128>>>(up_W, down_W, lin_W);

    // --- up layer 1 GEMM with FUSED layer-0 scalar GAT on A-load ---
    gemm_hmma<<<GEMM_GRID, 256, SMEM_GEMM>>>(nullptr,
        x, up_W0, up_b, edge_attr, WT(0), bufC);
    up_attn_k<<<NN / 8, 256>>>(bufC, up_as + HH, up_ad + HH, edge_attr, 1, up_b + HH, bufB);

    // --- up layer 2 -> x_up (bufA) ---
    gemm_hmma<<<GEMM_GRID, 256, SMEM_GEMM>>>(bufB, NO0, WT(1), bufC);
    up_attn_k<<<NN / 8, 256>>>(bufC, up_as + 2 * HH, up_ad + 2 * HH, edge_attr, 2,
                               up_b + 2 * HH, bufA);

    // --- down 0 GEMM: C0 = x_up @ down_W0 ---
    gemm_hmma<<<GEMM_GRID, 256, SMEM_GEMM>>>(bufA, NO0, WT(2), bufC);

    // --- loop i=0 fused: bufD = [relu(gather(bufC))+xup] @linW0 relu @downW0
    gemm_fused2<<<FGRID, 512, SMEM_FUSED>>>(bufC, bufA, down_b,
                                            WT(4), lin_b, WT(2), bufD);
    // --- loop i=1 fused: bufC = [relu(gather(bufD))+xup] @linW1 relu @downW1
    gemm_fused2<<<FGRID, 512, SMEM_FUSED>>>(bufD, bufA, down_b,
                                            WT(5), lin_b + HH, WT(3), bufC);

    // --- last down_attn fused with final dot (emb into d_out, dotv in bufB) ---
    down_final_k<<<NN / 8, 256>>>(bufC, down_b + HH, bufA, lin_lW, emb, bufB);

    // --- out[v] = dotv[v] - dotv[root] ---
    sub_k<<<NN / 256, 256>>>(bufB, out);
}

// round 13
// speedup vs baseline: 1.0350x; 1.0350x over previous
#include <cuda_runtime.h>
#include <cuda_bf16.h>
#include <cstdint>

#define NN 131072      // B*L nodes
#define LL 2048        // nodes per tree
#define HH 128         // hidden
#define LOG2L 11
#define GEMM_GRID 296  // 2 CTAs per SM x 148 SMs, persistent
#define NTILES 2048    // NN / 64
#define FTILES 1024    // NN / 128 (fused kernel, 128-row tiles)
#define FGRID 148

// ---------------- scratch (device globals; no allocation allowed) ----------
__device__ float g_bufA[NN * HH];   // x_up
__device__ float g_bufB[NN * HH];   // layer cur / dotv buffer
__device__ float g_bufC[NN * HH];   // gemm out
__device__ float g_bufD[NN * HH];   // fused chain ping-pong
__device__ float g_sc[NN * 2];      // per-node (h·a_s, h·a_d) scores
__device__ float g_coef[NN * 4];    // per-node softmax coefs (w1,w2,ws,0)
__device__ float g_pre[16];         // [0..11] w_e per up layer, [12]=W0·a_s, [13]=W0·a_d
__device__ __nv_bfloat16 g_wt[12 * 16384];  // 6 mats x {hi,lo} planes, transposed [n][k]

__device__ __forceinline__ float lrelu(float v) { return v > 0.f ? v : 0.2f * v; }
__device__ __forceinline__ float warpsum(float v) {
    #pragma unroll
    for (int o = 16; o; o >>= 1) v += __shfl_xor_sync(0xffffffffu, v, o);
    return v;
}
__device__ __forceinline__ float dot4(float4 a, float4 b) {
    return a.x * b.x + a.y * b.y + a.z * b.z + a.w * b.w;
}
__device__ __forceinline__ uint32_t smem_u32(const void* p) {
    uint32_t a;
    asm("{ .reg .u64 t; cvta.to.shared.u64 t, %1; cvt.u32.u64 %0, t; }" : "=r"(a) : "l"(p));
    return a;
}

// ======================= HMMA helpers (sm_80+ PTX) =========================
__device__ __forceinline__ void ldsm_x4(uint32_t* r, uint32_t addr) {
    asm volatile("ldmatrix.sync.aligned.m8n8.x4.shared.b16 {%0,%1,%2,%3}, [%4];"
                 : "=r"(r[0]), "=r"(r[1]), "=r"(r[2]), "=r"(r[3]) : "r"(addr));
}
__device__ __forceinline__ void mma16816(float* c, const uint32_t* a, const uint32_t* b) {
    asm volatile("mma.sync.aligned.m16n8k16.row.col.f32.bf16.bf16.f32 "
                 "{%0,%1,%2,%3}, {%4,%5,%6,%7}, {%8,%9}, {%0,%1,%2,%3};"
                 : "+f"(c[0]), "+f"(c[1]), "+f"(c[2]), "+f"(c[3])
                 : "r"(a[0]), "r"(a[1]), "r"(a[2]), "r"(a[3]), "r"(b[0]), "r"(b[1]));
}

// SMEM layout, plain GEMM (row stride 272 B)
#define A_HI 0
#define A_LO 17408
#define B_HI 34816
#define B_LO 69632
#define SC_OFF 104448      // 64 rows x 2 floats score scratch
#define SMEM_GEMM 104960
// SMEM layout, fused kernel (128-row A, two B matrices)
#define FA_HI 0
#define FA_LO 34816
#define FB1_HI 69632
#define FB1_LO 104448
#define FB2_HI 139264
#define FB2_LO 174080
#define SMEM_FUSED 208896

// ---------------- weight pre-conversion: W[k][n] -> hi/lo bf16 [n][k] ------
__global__ void wconv_k(const float* __restrict__ up_W,
                        const float* __restrict__ down_W,
                        const float* __restrict__ lin_W) {
    int bx = blockIdx.x;
    int mat = bx >> 7, n = bx & 127, k = threadIdx.x;
    const float* W = (mat < 2) ? up_W + mat * 16384
                   : (mat < 4) ? down_W + (mat - 2) * 16384
                               : lin_W + (mat - 4) * 16384;
    float w = W[k * 128 + n];
    __nv_bfloat16 hb = __float2bfloat16(w);
    float hf = __bfloat162float(hb);
    g_wt[(mat * 2 + 0) * 16384 + n * 128 + k] = hb;
    g_wt[(mat * 2 + 1) * 16384 + n * 128 + k] = __float2bfloat16(w - hf);
}

// ============== persistent HMMA GEMM: C = f(A) @ W, W loaded ONCE ==========
// A-load modes:
//   coef != 0 : A row v = relu(cf.x*h[c1] + cf.y*h[c2] + cf.z*h[v] + ub)
//               (GAT combine with PRECOMPUTED coefs — no expf, no reductions)
//               optionally mirrored to xup_out (fp32).
// Epilogue option:
//   sc_out != 0 : also emit per-row scores (C·avs, C·avd) via smem reduction.
__global__ void __launch_bounds__(256, 2)
gemm_hmma(const float* __restrict__ A, const float4* __restrict__ coef,
          const float* __restrict__ ub, float* __restrict__ xup_out,
          const float* __restrict__ avs, const float* __restrict__ avd,
          float* __restrict__ sc_out,
          const __nv_bfloat16* __restrict__ Wt, float* __restrict__ C) {
    extern __shared__ char smem[];
    uint32_t sb = smem_u32(smem);
    int tid = threadIdx.x;

    const uint4* Bh = (const uint4*)Wt;
    const uint4* Bl = (const uint4*)(Wt + 16384);
    #pragma unroll
    for (int i = tid; i < 2048; i += 256) {
        int n = i >> 4, kq = i & 15;
        uint32_t off = n * 272 + kq * 16;
        *(uint4*)(smem + B_HI + off) = Bh[i];
        *(uint4*)(smem + B_LO + off) = Bl[i];
    }

    int wid = tid >> 5, lane = tid & 31;
    int m0 = (wid & 1) * 32, n0 = (wid >> 1) * 32;
    int g = lane >> 3, r = lane & 7;
    uint32_t aoff0 = (uint32_t)((m0 + (g & 1) * 8 + r) * 272 + (g >> 1) * 16);
    uint32_t boff0 = (uint32_t)((n0 + (g >> 1) * 8 + r) * 272 + (g & 1) * 16);
    int cr = lane >> 2, cc = (lane & 3) * 2;

    // per-thread fixed score weights (cols fixed across tiles)
    float as_r[4][2], ad_r[4][2];
    if (sc_out) {
        #pragma unroll
        for (int nf = 0; nf < 4; nf++) {
            int col = n0 + nf * 8 + cc;
            as_r[nf][0] = avs[col]; as_r[nf][1] = avs[col + 1];
            ad_r[nf][0] = avd[col]; ad_r[nf][1] = avd[col + 1];
        }
    }

    for (int tile = blockIdx.x; tile < NTILES; tile += GEMM_GRID) {
        if (sc_out && tid < 128)
            *(float*)(smem + SC_OFF + tid * 4) = 0.f;
        #pragma unroll
        for (int i = tid; i < 2048; i += 256) {
            int row = i >> 5, c4 = i & 31;
            float4 v;
            if (coef) {
                int vv = tile * 64 + row;
                int l = vv & (LL - 1);
                float4 cf = coef[vv];
                int c1 = (l <= 1023) ? vv + l + 1 : vv;
                int c2 = (l <= 1022) ? vv + l + 2 : vv;
                const float4* H = (const float4*)A;
                float4 h1 = H[(size_t)c1 * 32 + c4];
                float4 h2 = H[(size_t)c2 * 32 + c4];
                float4 hv = H[(size_t)vv * 32 + c4];
                float4 b4 = ((const float4*)ub)[c4];
                v.x = fmaxf(cf.x * h1.x + cf.y * h2.x + cf.z * hv.x + b4.x, 0.f);
                v.y = fmaxf(cf.x * h1.y + cf.y * h2.y + cf.z * hv.y + b4.y, 0.f);
                v.z = fmaxf(cf.x * h1.z + cf.y * h2.z + cf.z * hv.z + b4.z, 0.f);
                v.w = fmaxf(cf.x * h1.w + cf.y * h2.w + cf.z * hv.w + b4.w, 0.f);
                if (xup_out) ((float4*)xup_out)[(size_t)vv * 32 + c4] = v;
            } else {
                v = ((const float4*)(A + (size_t)tile * 64 * 128))[i];
            }
            float f[4] = {v.x, v.y, v.z, v.w};
            union { uint2 u; __nv_bfloat16 h[4]; } ph, pl;
            #pragma unroll
            for (int e = 0; e < 4; e++) {
                __nv_bfloat16 hb = __float2bfloat16(f[e]);
                ph.h[e] = hb;
                pl.h[e] = __float2bfloat16(f[e] - __bfloat162float(hb));
            }
            uint32_t off = row * 272 + c4 * 8;
            *(uint2*)(smem + A_HI + off) = ph.u;
            *(uint2*)(smem + A_LO + off) = pl.u;
        }
        __syncthreads();

        float acc[2][4][4];
        #pragma unroll
        for (int a = 0; a < 2; a++)
            #pragma unroll
            for (int b = 0; b < 4; b++)
                #pragma unroll
                for (int c = 0; c < 4; c++) acc[a][b][c] = 0.f;

        #pragma unroll 4
        for (int k16 = 0; k16 < 8; k16++) {
            uint32_t ah[2][4], al[2][4], bh[4][2];
            ldsm_x4(ah[0], sb + A_HI + aoff0 + k16 * 32);
            ldsm_x4(ah[1], sb + A_HI + aoff0 + 16 * 272 + k16 * 32);
            ldsm_x4(al[0], sb + A_LO + aoff0 + k16 * 32);
            ldsm_x4(al[1], sb + A_LO + aoff0 + 16 * 272 + k16 * 32);
            ldsm_x4(&bh[0][0], sb + B_HI + boff0 + k16 * 32);
            ldsm_x4(&bh[2][0], sb + B_HI + boff0 + 16 * 272 + k16 * 32);
            #pragma unroll
            for (int mf = 0; mf < 2; mf++)
                #pragma unroll
                for (int nf = 0; nf < 4; nf++)
                    mma16816(acc[mf][nf], ah[mf], bh[nf]);
            #pragma unroll
            for (int mf = 0; mf < 2; mf++)
                #pragma unroll
                for (int nf = 0; nf < 4; nf++)
                    mma16816(acc[mf][nf], al[mf], bh[nf]);
        }
        #pragma unroll 4
        for (int k16 = 0; k16 < 8; k16++) {
            uint32_t ah[2][4], bl[4][2];
            ldsm_x4(ah[0], sb + A_HI + aoff0 + k16 * 32);
            ldsm_x4(ah[1], sb + A_HI + aoff0 + 16 * 272 + k16 * 32);
            ldsm_x4(&bl[0][0], sb + B_LO + boff0 + k16 * 32);
            ldsm_x4(&bl[2][0], sb + B_LO + boff0 + 16 * 272 + k16 * 32);
            #pragma unroll
            for (int mf = 0; mf < 2; mf++)
                #pragma unroll
                for (int nf = 0; nf < 4; nf++)
                    mma16816(acc[mf][nf], ah[mf], bl[nf]);
        }

        size_t rbase = (size_t)tile * 64;
        #pragma unroll
        for (int mf = 0; mf < 2; mf++) {
            #pragma unroll
            for (int nf = 0; nf < 4; nf++) {
                int col = n0 + nf * 8 + cc;
                int row0 = m0 + mf * 16 + cr;
                *(float2*)(C + (rbase + row0) * 128 + col) =
                    make_float2(acc[mf][nf][0], acc[mf][nf][1]);
                *(float2*)(C + (rbase + row0 + 8) * 128 + col) =
                    make_float2(acc[mf][nf][2], acc[mf][nf][3]);
            }
        }

        // ---- optional score epilogue: sc[r] = (C_row·avs, C_row·avd) ----
        if (sc_out) {
            #pragma unroll
            for (int mf = 0; mf < 2; mf++) {
                #pragma unroll
                for (int j = 0; j < 2; j++) {
                    int rrow = m0 + mf * 16 + cr + j * 8;
                    float ps = 0.f, pd = 0.f;
                    #pragma unroll
                    for (int nf = 0; nf < 4; nf++) {
                        float a0 = acc[mf][nf][2 * j + 0];
                        float a1 = acc[mf][nf][2 * j + 1];
                        ps += a0 * as_r[nf][0] + a1 * as_r[nf][1];
                        pd += a0 * ad_r[nf][0] + a1 * ad_r[nf][1];
                    }
                    ps += __shfl_xor_sync(0xffffffffu, ps, 1);
                    ps += __shfl_xor_sync(0xffffffffu, ps, 2);
                    pd += __shfl_xor_sync(0xffffffffu, pd, 1);
                    pd += __shfl_xor_sync(0xffffffffu, pd, 2);
                    if ((lane & 3) == 0) {
                        atomicAdd((float*)(smem + SC_OFF + (rrow * 2 + 0) * 4), ps);
                        atomicAdd((float*)(smem + SC_OFF + (rrow * 2 + 1) * 4), pd);
                    }
                }
            }
            __syncthreads();
            if (tid < 128)
                sc_out[(rbase + (tid >> 1)) * 2 + (tid & 1)] =
                    *(float*)(smem + SC_OFF + tid * 4);
        }
        __syncthreads();
    }
}

// ---- coef_k: per-node softmax coefs from scores + edge dots (high occ) ----
__global__ void coef_k(const float* __restrict__ sc, const float* __restrict__ edge_attr,
                       int layer, float4* __restrict__ coef) {
    int v = blockIdx.x * 256 + threadIdx.x;
    int l = v & (LL - 1), bi = v >> LOG2L;
    int nc = (l < 1023) ? 2 : ((l == 1023) ? 1 : 0);
    if (nc == 0) { coef[v] = make_float4(0.f, 0.f, 1.f, 0.f); return; }
    float svx = sc[v * 2 + 0], svy = sc[v * 2 + 1];
    int c1 = v + l + 1;
    float s1src = sc[(size_t)c1 * 2];
    float s2src = (nc == 2) ? sc[(size_t)(c1 + 1) * 2] : 0.f;
    const float* we = g_pre + layer * 4;
    long e1 = (long)bi * 2047 + 2 * l;
    const float* ea1 = edge_attr + e1 * 4;
    float e1s = ea1[0] * we[0] + ea1[1] * we[1] + ea1[2] * we[2] + ea1[3] * we[3];
    float e2s = 0.f;
    if (nc == 2) {
        const float* ea2 = ea1 + 4;
        e2s = ea2[0] * we[0] + ea2[1] * we[1] + ea2[2] * we[2] + ea2[3] * we[3];
    }
    float s1 = lrelu(s1src + svy + e1s);
    float s2 = (nc == 2) ? lrelu(s2src + svy + e2s) : -1e30f;
    float emean = (nc == 2) ? 0.5f * (e1s + e2s) : e1s;
    float ss = lrelu(svx + svy + emean);
    float m = fmaxf(ss, fmaxf(s1, s2));
    float w1 = __expf(s1 - m);
    float w2 = (nc == 2) ? __expf(s2 - m) : 0.f;
    float ws = __expf(ss - m);
    float inv = 1.f / (w1 + w2 + ws);
    coef[v] = make_float4(w1 * inv, w2 * inv, ws * inv, 0.f);
}

// ====== fused lin+down chain (unchanged from R11) ==========================
__global__ void __launch_bounds__(512, 1)
gemm_fused2(const float* __restrict__ gC, const float* __restrict__ xup,
            const float* __restrict__ dbias,
            const __nv_bfloat16* __restrict__ Wt1, const float* __restrict__ lbias,
            const __nv_bfloat16* __restrict__ Wt2,
            float* __restrict__ out) {
    extern __shared__ char smem[];
    uint32_t sb = smem_u32(smem);
    int tid = threadIdx.x;

    {
        const uint4* B1h = (const uint4*)Wt1;
        const uint4* B1l = (const uint4*)(Wt1 + 16384);
        const uint4* B2h = (const uint4*)Wt2;
        const uint4* B2l = (const uint4*)(Wt2 + 16384);
        #pragma unroll
        for (int i = tid; i < 2048; i += 512) {
            int n = i >> 4, kq = i & 15;
            uint32_t off = n * 272 + kq * 16;
            *(uint4*)(smem + FB1_HI + off) = B1h[i];
            *(uint4*)(smem + FB1_LO + off) = B1l[i];
            *(uint4*)(smem + FB2_HI + off) = B2h[i];
            *(uint4*)(smem + FB2_LO + off) = B2l[i];
        }
    }

    int wid = tid >> 5, lane = tid & 31;
    int m0 = (wid & 3) * 32, n0 = (wid >> 2) * 32;
    int g = lane >> 3, r = lane & 7;
    uint32_t aoff0 = (uint32_t)((m0 + (g & 1) * 8 + r) * 272 + (g >> 1) * 16);
    uint32_t boff0 = (uint32_t)((n0 + (g >> 1) * 8 + r) * 272 + (g & 1) * 16);
    int cr = lane >> 2, cc = (lane & 3) * 2;

    for (int tile = blockIdx.x; tile < FTILES; tile += FGRID) {
        #pragma unroll
        for (int i = tid; i < 4096; i += 512) {
            int row = i >> 5, c4 = i & 31;
            int vv = tile * 128 + row;
            int l = vv & (LL - 1);
            float4 b4 = ((const float4*)dbias)[c4];
            float4 xu = ((const float4*)xup)[(size_t)vv * 32 + c4];
            float4 v;
            if (l == 0) {
                v.x = fmaxf(b4.x, 0.f) + xu.x;
                v.y = fmaxf(b4.y, 0.f) + xu.y;
                v.z = fmaxf(b4.z, 0.f) + xu.z;
                v.w = fmaxf(b4.w, 0.f) + xu.w;
            } else {
                int p = vv - l + ((l - 1) >> 1);
                float4 cp = ((const float4*)gC)[(size_t)p * 32 + c4];
                v.x = fmaxf(cp.x + b4.x, 0.f) + xu.x;
                v.y = fmaxf(cp.y + b4.y, 0.f) + xu.y;
                v.z = fmaxf(cp.z + b4.z, 0.f) + xu.z;
                v.w = fmaxf(cp.w + b4.w, 0.f) + xu.w;
            }
            float f[4] = {v.x, v.y, v.z, v.w};
            union { uint2 u; __nv_bfloat16 h[4]; } ph, pl;
            #pragma unroll
            for (int e = 0; e < 4; e++) {
                __nv_bfloat16 hb = __float2bfloat16(f[e]);
                ph.h[e] = hb;
                pl.h[e] = __float2bfloat16(f[e] - __bfloat162float(hb));
            }
            uint32_t off = row * 272 + c4 * 8;
            *(uint2*)(smem + FA_HI + off) = ph.u;
            *(uint2*)(smem + FA_LO + off) = pl.u;
        }
        __syncthreads();

        float acc[2][4][4];
        #pragma unroll
        for (int a = 0; a < 2; a++)
            #pragma unroll
            for (int b = 0; b < 4; b++)
                #pragma unroll
                for (int c = 0; c < 4; c++) acc[a][b][c] = 0.f;

        #pragma unroll 4
        for (int k16 = 0; k16 < 8; k16++) {
            uint32_t ah[2][4], al[2][4], bh[4][2];
            ldsm_x4(ah[0], sb + FA_HI + aoff0 + k16 * 32);
            ldsm_x4(ah[1], sb + FA_HI + aoff0 + 16 * 272 + k16 * 32);
            ldsm_x4(al[0], sb + FA_LO + aoff0 + k16 * 32);
            ldsm_x4(al[1], sb + FA_LO + aoff0 + 16 * 272 + k16 * 32);
            ldsm_x4(&bh[0][0], sb + FB1_HI + boff0 + k16 * 32);
            ldsm_x4(&bh[2][0], sb + FB1_HI + boff0 + 16 * 272 + k16 * 32);
            #pragma unroll
            for (int mf = 0; mf < 2; mf++)
                #pragma unroll
                for (int nf = 0; nf < 4; nf++)
                    mma16816(acc[mf][nf], ah[mf], bh[nf]);
            #pragma unroll
            for (int mf = 0; mf < 2; mf++)
                #pragma unroll
                for (int nf = 0; nf < 4; nf++)
                    mma16816(acc[mf][nf], al[mf], bh[nf]);
        }
        #pragma unroll 4
        for (int k16 = 0; k16 < 8; k16++) {
            uint32_t ah[2][4], bl[4][2];
            ldsm_x4(ah[0], sb + FA_HI + aoff0 + k16 * 32);
            ldsm_x4(ah[1], sb + FA_HI + aoff0 + 16 * 272 + k16 * 32);
            ldsm_x4(&bl[0][0], sb + FB1_LO + boff0 + k16 * 32);
            ldsm_x4(&bl[2][0], sb + FB1_LO + boff0 + 16 * 272 + k16 * 32);
            #pragma unroll
            for (int mf = 0; mf < 2; mf++)
                #pragma unroll
                for (int nf = 0; nf < 4; nf++)
                    mma16816(acc[mf][nf], ah[mf], bl[nf]);
        }
        __syncthreads();

        #pragma unroll
        for (int mf = 0; mf < 2; mf++) {
            #pragma unroll
            for (int nf = 0; nf < 4; nf++) {
                int col = n0 + nf * 8 + cc;
                float bx = lbias[col], by = lbias[col + 1];
                #pragma unroll
                for (int j = 0; j < 2; j++) {
                    int row = m0 + mf * 16 + cr + j * 8;
                    float f0 = fmaxf(acc[mf][nf][2 * j + 0] + bx, 0.f);
                    float f1 = fmaxf(acc[mf][nf][2 * j + 1] + by, 0.f);
                    union { uint32_t u; __nv_bfloat16 h[2]; } uh, ul;
                    uh.h[0] = __float2bfloat16(f0);
                    uh.h[1] = __float2bfloat16(f1);
                    ul.h[0] = __float2bfloat16(f0 - __bfloat162float(uh.h[0]));
                    ul.h[1] = __float2bfloat16(f1 - __bfloat162float(uh.h[1]));
                    uint32_t off = row * 272 + col * 2;
                    *(uint32_t*)(smem + FA_HI + off) = uh.u;
                    *(uint32_t*)(smem + FA_LO + off) = ul.u;
                }
            }
        }
        __syncthreads();

        #pragma unroll
        for (int a = 0; a < 2; a++)
            #pragma unroll
            for (int b = 0; b < 4; b++)
                #pragma unroll
                for (int c = 0; c < 4; c++) acc[a][b][c] = 0.f;

        #pragma unroll 4
        for (int k16 = 0; k16 < 8; k16++) {
            uint32_t ah[2][4], al[2][4], bh[4][2];
            ldsm_x4(ah[0], sb + FA_HI + aoff0 + k16 * 32);
            ldsm_x4(ah[1], sb + FA_HI + aoff0 + 16 * 272 + k16 * 32);
            ldsm_x4(al[0], sb + FA_LO + aoff0 + k16 * 32);
            ldsm_x4(al[1], sb + FA_LO + aoff0 + 16 * 272 + k16 * 32);
            ldsm_x4(&bh[0][0], sb + FB2_HI + boff0 + k16 * 32);
            ldsm_x4(&bh[2][0], sb + FB2_HI + boff0 + 16 * 272 + k16 * 32);
            #pragma unroll
            for (int mf = 0; mf < 2; mf++)
                #pragma unroll
                for (int nf = 0; nf < 4; nf++)
                    mma16816(acc[mf][nf], ah[mf], bh[nf]);
            #pragma unroll
            for (int mf = 0; mf < 2; mf++)
                #pragma unroll
                for (int nf = 0; nf < 4; nf++)
                    mma16816(acc[mf][nf], al[mf], bh[nf]);
        }
        #pragma unroll 4
        for (int k16 = 0; k16 < 8; k16++) {
            uint32_t ah[2][4], bl[4][2];
            ldsm_x4(ah[0], sb + FA_HI + aoff0 + k16 * 32);
            ldsm_x4(ah[1], sb + FA_HI + aoff0 + 16 * 272 + k16 * 32);
            ldsm_x4(&bl[0][0], sb + FB2_LO + boff0 + k16 * 32);
            ldsm_x4(&bl[2][0], sb + FB2_LO + boff0 + 16 * 272 + k16 * 32);
            #pragma unroll
            for (int mf = 0; mf < 2; mf++)
                #pragma unroll
                for (int nf = 0; nf < 4; nf++)
                    mma16816(acc[mf][nf], ah[mf], bl[nf]);
        }

        size_t rbase = (size_t)tile * 128;
        #pragma unroll
        for (int mf = 0; mf < 2; mf++) {
            #pragma unroll
            for (int nf = 0; nf < 4; nf++) {
                int col = n0 + nf * 8 + cc;
                int row0 = m0 + mf * 16 + cr;
                *(float2*)(out + (rbase + row0) * 128 + col) =
                    make_float2(acc[mf][nf][0], acc[mf][nf][1]);
                *(float2*)(out + (rbase + row0 + 8) * 128 + col) =
                    make_float2(acc[mf][nf][2], acc[mf][nf][3]);
            }
        }
        __syncthreads();
    }
}

// ---------------- tiny precompute: w_e = We @ a_e per up layer, W0 dots ----
__global__ void precompute_k(const float* __restrict__ up_We,
                             const float* __restrict__ up_ae,
                             const float* __restrict__ up_W0,
                             const float* __restrict__ as0,
                             const float* __restrict__ ad0) {
    int lane = threadIdx.x;
    for (int i = 0; i < 3; i++) {
        for (int d = 0; d < 4; d++) {
            float s = 0.f;
            for (int t = lane; t < HH; t += 32)
                s += up_We[(i * 4 + d) * HH + t] * up_ae[i * HH + t];
            s = warpsum(s);
            if (lane == 0) g_pre[i * 4 + d] = s;
        }
    }
    float s = 0.f;
    for (int t = lane; t < HH; t += 32) s += up_W0[t] * as0[t];
    s = warpsum(s);
    if (lane == 0) g_pre[12] = s;
    s = 0.f;
    for (int t = lane; t < HH; t += 32) s += up_W0[t] * ad0[t];
    s = warpsum(s);
    if (lane == 0) g_pre[13] = s;
}

// ---------------- up layer 0: W0 is (1,H) -> scalar attn, warp per node ----
__global__ void up0_k(const float* __restrict__ x, const float* __restrict__ W0,
                      const float* __restrict__ bias,
                      const float* __restrict__ edge_attr,
                      float* __restrict__ out) {
    int w = threadIdx.x >> 5, lane = threadIdx.x & 31;
    int v = blockIdx.x * 8 + w;
    int l = v & (LL - 1), bi = v >> LOG2L;
    float xv = x[v];
    int nc = (l < 1023) ? 2 : ((l == 1023) ? 1 : 0);
    float comb;
    if (nc == 0) {
        comb = xv;
    } else {
        float was = g_pre[12], wad = g_pre[13];
        float we0 = g_pre[0], we1 = g_pre[1], we2 = g_pre[2], we3 = g_pre[3];
        int c1 = v + l + 1;
        float x1 = x[c1];
        float x2 = (nc == 2) ? x[c1 + 1] : 0.f;
        long e1 = (long)bi * 2047 + 2 * l;
        const float* ea1 = edge_attr + e1 * 4;
        float e1s = ea1[0] * we0 + ea1[1] * we1 + ea1[2] * we2 + ea1[3] * we3;
        float e2s = 0.f;
        if (nc == 2) {
            const float* ea2 = ea1 + 4;
            e2s = ea2[0] * we0 + ea2[1] * we1 + ea2[2] * we2 + ea2[3] * we3;
        }
        float adv = xv * wad;
        float s1 = lrelu(x1 * was + adv + e1s);
        float s2 = (nc == 2) ? lrelu(x2 * was + adv + e2s) : -1e30f;
        float emean = (nc == 2) ? 0.5f * (e1s + e2s) : e1s;
        float ss = lrelu(xv * was + adv + emean);
        float m = fmaxf(ss, fmaxf(s1, s2));
        float w1 = __expf(s1 - m);
        float w2 = (nc == 2) ? __expf(s2 - m) : 0.f;
        float ws = __expf(ss - m);
        comb = (w1 * x1 + w2 * x2 + ws * xv) / (w1 + w2 + ws);
    }
    float4 w0 = ((const float4*)W0)[lane];
    float4 b4 = ((const float4*)bias)[lane];
    float4 o;
    o.x = fmaxf(comb * w0.x + b4.x, 0.f);
    o.y = fmaxf(comb * w0.y + b4.y, 0.f);
    o.z = fmaxf(comb * w0.z + b4.z, 0.f);
    o.w = fmaxf(comb * w0.w + b4.w, 0.f);
    ((float4*)(out + (size_t)v * HH))[lane] = o;
}

// ------- last down_attn fused with final dot: warp per node ---------------
__global__ void down_final_k(const float* __restrict__ h, const float* __restrict__ bias,
                             const float* __restrict__ x_up, const float* __restrict__ wlast,
                             float* __restrict__ emb, float* __restrict__ dotv) {
    int w = threadIdx.x >> 5, lane = threadIdx.x & 31;
    int v = blockIdx.x * 8 + w;
    int l = v & (LL - 1);
    float4 xu = ((const float4*)x_up)[(size_t)v * 32 + lane];
    float4 b4 = ((const float4*)bias)[lane];
    float4 val;
    if (l == 0) val = b4;
    else {
        int p = v - l + ((l - 1) >> 1);
        float4 hp = ((const float4*)h)[(size_t)p * 32 + lane];
        val.x = hp.x + b4.x; val.y = hp.y + b4.y;
        val.z = hp.z + b4.z; val.w = hp.w + b4.w;
    }
    float4 o;
    o.x = fmaxf(val.x, 0.f) + xu.x;
    o.y = fmaxf(val.y, 0.f) + xu.y;
    o.z = fmaxf(val.z, 0.f) + xu.z;
    o.w = fmaxf(val.w, 0.f) + xu.w;
    ((float4*)(emb + (size_t)v * HH))[lane] = o;
    float4 w4 = ((const float4*)wlast)[lane];
    float q = warpsum(dot4(o, w4));
    if (lane == 0) dotv[v] = q;
}

// ---------------- out[v] = dotv[v] - dotv[root(v)] -------------------------
__global__ void sub_k(const float* __restrict__ dotv, float* __restrict__ out) {
    int v = blockIdx.x * 256 + threadIdx.x;
    out[v] = dotv[v] - dotv[v & ~(LL - 1)];
}

// ---------------------------------------------------------------------------
extern "C" void kernel_launch(void* const* d_in, const int* in_sizes, int n_in,
                              void* d_out, int out_size) {
    const float* x         = (const float*)d_in[0];
    const float* edge_attr = (const float*)d_in[3];
    const float* up_W0     = (const float*)d_in[4];
    const float* up_W      = (const float*)d_in[5];
    const float* up_as     = (const float*)d_in[6];
    const float* up_ad     = (const float*)d_in[7];
    const float* up_We     = (const float*)d_in[8];
    const float* up_ae     = (const float*)d_in[9];
    const float* up_b      = (const float*)d_in[10];
    const float* down_W    = (const float*)d_in[11];
    const float* down_b    = (const float*)d_in[16];
    const float* lin_W     = (const float*)d_in[17];
    const float* lin_b     = (const float*)d_in[18];
    const float* lin_lW    = (const float*)d_in[19];

    float *bufA, *bufB, *bufC, *bufD, *sc, *coef;
    __nv_bfloat16* wt;
    cudaGetSymbolAddress((void**)&bufA, g_bufA);
    cudaGetSymbolAddress((void**)&bufB, g_bufB);
    cudaGetSymbolAddress((void**)&bufC, g_bufC);
    cudaGetSymbolAddress((void**)&bufD, g_bufD);
    cudaGetSymbolAddress((void**)&sc, g_sc);
    cudaGetSymbolAddress((void**)&coef, g_coef);
    cudaGetSymbolAddress((void**)&wt, g_wt);

    cudaFuncSetAttribute(gemm_hmma, cudaFuncAttributeMaxDynamicSharedMemorySize,
                         SMEM_GEMM);
    cudaFuncSetAttribute(gemm_fused2, cudaFuncAttributeMaxDynamicSharedMemorySize,
                         SMEM_FUSED);

    float* out = (float*)d_out;
    float* emb = out + NN;   // output tuple: (out[B*L], emb[B*L*H]) concatenated

    // mats: 0,1 = up_W[0..1]; 2,3 = down_W[0..1]; 4,5 = lin_W[0..1]
    #define WT(m) (wt + (m) * 2 * 16384)

    precompute_k<<<1, 32>>>(up_We, up_ae, up_W0, up_as, up_ad);
    wconv_k<<<768, 128>>>(up_W, down_W, lin_W);

    // --- up layer 0 (standalone, high occupancy) ---
    up0_k<<<NN / 8, 256>>>(x, up_W0, up_b, edge_attr, bufB);

    // --- gemm1: h1 = h0 @ up_W1, emitting layer-1 attention scores ---
    gemm_hmma<<<GEMM_GRID, 256, SMEM_GEMM>>>(bufB, nullptr, nullptr, nullptr,
        up_as + HH, up_ad + HH, sc, WT(0), bufC);
    coef_k<<<NN / 256, 256>>>(sc, edge_attr, 1, (float4*)coef);

    // --- gemm2: h2 = attn1(h1) @ up_W2 (attn in A-load), layer-2 scores ---
    gemm_hmma<<<GEMM_GRID, 256, SMEM_GEMM>>>(bufC, (const float4*)coef, up_b + HH,
        nullptr, up_as + 2 * HH, up_ad + 2 * HH, sc, WT(1), bufD);
    coef_k<<<NN / 256, 256>>>(sc, edge_attr, 2, (float4*)coef);

    // --- gemm3 (down0): A = x_up = attn2(h2) (A-load, mirrored to bufA) ---
    gemm_hmma<<<GEMM_GRID, 256, SMEM_GEMM>>>(bufD, (const float4*)coef,
        up_b + 2 * HH, bufA, nullptr, nullptr, nullptr, WT(2), bufC);

    // --- loop i=0 fused: bufD = [relu(gather(bufC))+xup] @linW0 relu @downW0
    gemm_fused2<<<FGRID, 512, SMEM_FUSED>>>(bufC, bufA, down_b,
                                            WT(4), lin_b, WT(2), bufD);
    // --- loop i=1 fused: bufC = [relu(gather(bufD))+xup] @linW1 relu @downW1
    gemm_fused2<<<FGRID, 512, SMEM_FUSED>>>(bufD, bufA, down_b,
                                            WT(5), lin_b + HH, WT(3), bufC);

    // --- last down_attn fused with final dot (emb into d_out, dotv in bufB) ---
    down_final_k<<<NN / 8, 256>>>(bufC, down_b + HH, bufA, lin_lW, emb, bufB);

    // --- out[v] = dotv[v] - dotv[root] ---
    sub_k<<<NN / 256, 256>>>(bufB, out);
}

// round 14
// speedup vs baseline: 1.0682x; 1.0321x over previous
#include <cuda_runtime.h>
#include <cuda_bf16.h>
#include <cstdint>

#define NN 131072      // B*L nodes
#define LL 2048        // nodes per tree
#define HH 128         // hidden
#define LOG2L 11
#define GEMM_GRID 296  // 2 CTAs per SM x 148 SMs, persistent
#define NTILES 2048    // NN / 64
#define FTILES 1024    // NN / 128 (fused kernel, 128-row tiles)
#define FGRID 148

// ---------------- scratch (device globals; no allocation allowed) ----------
__device__ float g_bufA[NN * HH];   // x_up
__device__ float g_bufB[NN * HH];   // layer cur / dotv buffer
__device__ float g_bufC[NN * HH];   // gemm out
__device__ float g_bufD[NN * HH];   // fused chain ping-pong
__device__ float g_pre[16];         // [0..11] w_e per up layer, [12]=W0·a_s, [13]=W0·a_d
__device__ float g_thr[128];        // sorted relu breakpoints for layer0+gemm1
__device__ float g_tabU[129 * 128]; // per-interval affine slope table
__device__ float g_tabV[129 * 128]; // per-interval affine offset table
__device__ __nv_bfloat16 g_wt[12 * 16384];  // 6 mats x {hi,lo} planes, transposed [n][k]

__device__ __forceinline__ float lrelu(float v) { return v > 0.f ? v : 0.2f * v; }
__device__ __forceinline__ float warpsum(float v) {
    #pragma unroll
    for (int o = 16; o; o >>= 1) v += __shfl_xor_sync(0xffffffffu, v, o);
    return v;
}
__device__ __forceinline__ float dot4(float4 a, float4 b) {
    return a.x * b.x + a.y * b.y + a.z * b.z + a.w * b.w;
}
__device__ __forceinline__ uint32_t smem_u32(const void* p) {
    uint32_t a;
    asm("{ .reg .u64 t; cvta.to.shared.u64 t, %1; cvt.u32.u64 %0, t; }" : "=r"(a) : "l"(p));
    return a;
}

// ======================= HMMA helpers (sm_80+ PTX) =========================
__device__ __forceinline__ void ldsm_x4(uint32_t* r, uint32_t addr) {
    asm volatile("ldmatrix.sync.aligned.m8n8.x4.shared.b16 {%0,%1,%2,%3}, [%4];"
                 : "=r"(r[0]), "=r"(r[1]), "=r"(r[2]), "=r"(r[3]) : "r"(addr));
}
__device__ __forceinline__ void mma16816(float* c, const uint32_t* a, const uint32_t* b) {
    asm volatile("mma.sync.aligned.m16n8k16.row.col.f32.bf16.bf16.f32 "
                 "{%0,%1,%2,%3}, {%4,%5,%6,%7}, {%8,%9}, {%0,%1,%2,%3};"
                 : "+f"(c[0]), "+f"(c[1]), "+f"(c[2]), "+f"(c[3])
                 : "r"(a[0]), "r"(a[1]), "r"(a[2]), "r"(a[3]), "r"(b[0]), "r"(b[1]));
}

// SMEM layout, plain GEMM (row stride 272 B)
#define A_HI 0
#define A_LO 17408
#define B_HI 34816
#define B_LO 69632
#define SMEM_GEMM 104448
// SMEM layout, fused kernel (128-row A, two B matrices)
#define FA_HI 0
#define FA_LO 34816
#define FB1_HI 69632
#define FB1_LO 104448
#define FB2_HI 139264
#define FB2_LO 174080
#define SMEM_FUSED 208896

// ---------------- weight pre-conversion: W[k][n] -> hi/lo bf16 [n][k] ------
__global__ void wconv_k(const float* __restrict__ up_W,
                        const float* __restrict__ down_W,
                        const float* __restrict__ lin_W) {
    int bx = blockIdx.x;
    int mat = bx >> 7, n = bx & 127, k = threadIdx.x;
    const float* W = (mat < 2) ? up_W + mat * 16384
                   : (mat < 4) ? down_W + (mat - 2) * 16384
                               : lin_W + (mat - 4) * 16384;
    float w = W[k * 128 + n];
    __nv_bfloat16 hb = __float2bfloat16(w);
    float hf = __bfloat162float(hb);
    g_wt[(mat * 2 + 0) * 16384 + n * 128 + k] = hb;
    g_wt[(mat * 2 + 1) * 16384 + n * 128 + k] = __float2bfloat16(w - hf);
}

// ---- precompute2: piecewise-linear tables for C1(comb) = relu(comb*W0+b)@W1
// relu(comb*W0[j]+b[j]) toggles at t_j = -b[j]/W0[j]. Sweep sorted breakpoints
// accumulating (U,V) so that C1[v,n] = comb*U_i[n] + V_i[n], i = #{t < comb}.
__global__ void precompute2_k(const float* __restrict__ W0,
                              const float* __restrict__ ub,
                              const float* __restrict__ W1) {
    __shared__ float t[128], w0s[128], bs[128];
    __shared__ int ord[128];
    int j = threadIdx.x;   // 128 threads
    float w0 = W0[j], b = ub[j];
    float tj = (w0 != 0.f) ? (-b / w0) : 3.0e38f;
    t[j] = tj; w0s[j] = w0; bs[j] = b;
    __syncthreads();
    int rank = 0;
    for (int k = 0; k < 128; k++) {
        float tk = t[k];
        if (tk < tj || (tk == tj && k < j)) rank++;
    }
    ord[rank] = j;
    g_thr[rank] = tj;
    __syncthreads();
    // thread j now acts as output column n
    int n = j;
    float U = 0.f, V = 0.f;
    for (int k = 0; k < 128; k++) {          // interval 0: comb below all t
        float w1 = W1[k * 128 + n];
        if (w0s[k] < 0.f)      { U += w0s[k] * w1; V += bs[k] * w1; }
        else if (w0s[k] == 0.f && bs[k] > 0.f) V += bs[k] * w1;
    }
    g_tabU[n] = U; g_tabV[n] = V;
    for (int i = 0; i < 128; i++) {
        int jj = ord[i];
        float w0j = w0s[jj], bj = bs[jj], w1 = W1[jj * 128 + n];
        if (w0j > 0.f)      { U += w0j * w1; V += bj * w1; }
        else if (w0j < 0.f) { U -= w0j * w1; V -= bj * w1; }
        g_tabU[(i + 1) * 128 + n] = U;
        g_tabV[(i + 1) * 128 + n] = V;
    }
}

// ---- layer1_k: C1[v,:] = comb(v)*U_i + V_i  (replaces up0_k + gemm1) ------
__global__ void layer1_k(const float* __restrict__ x,
                         const float* __restrict__ edge_attr,
                         float* __restrict__ out) {
    int w = threadIdx.x >> 5, lane = threadIdx.x & 31;
    int v = blockIdx.x * 8 + w;
    int l = v & (LL - 1), bi = v >> LOG2L;
    float xv = x[v];
    int nc = (l < 1023) ? 2 : ((l == 1023) ? 1 : 0);
    float comb;
    if (nc == 0) {
        comb = xv;
    } else {
        float was = g_pre[12], wad = g_pre[13];
        int c1 = v + l + 1;
        float x1 = x[c1];
        float x2 = (nc == 2) ? x[c1 + 1] : 0.f;
        long e1 = (long)bi * 2047 + 2 * l;
        const float* ea1 = edge_attr + e1 * 4;
        float e1s = ea1[0] * g_pre[0] + ea1[1] * g_pre[1] +
                    ea1[2] * g_pre[2] + ea1[3] * g_pre[3];
        float e2s = 0.f;
        if (nc == 2) {
            const float* ea2 = ea1 + 4;
            e2s = ea2[0] * g_pre[0] + ea2[1] * g_pre[1] +
                  ea2[2] * g_pre[2] + ea2[3] * g_pre[3];
        }
        float adv = xv * wad;
        float s1 = lrelu(x1 * was + adv + e1s);
        float s2 = (nc == 2) ? lrelu(x2 * was + adv + e2s) : -1e30f;
        float emean = (nc == 2) ? 0.5f * (e1s + e2s) : e1s;
        float ss = lrelu(xv * was + adv + emean);
        float m = fmaxf(ss, fmaxf(s1, s2));
        float w1 = __expf(s1 - m);
        float w2 = (nc == 2) ? __expf(s2 - m) : 0.f;
        float ws = __expf(ss - m);
        comb = (w1 * x1 + w2 * x2 + ws * xv) / (w1 + w2 + ws);
    }
    // interval index: count of sorted thresholds below comb (warp ballot-free)
    float cnt = (g_thr[lane] < comb ? 1.f : 0.f) +
                (g_thr[lane + 32] < comb ? 1.f : 0.f) +
                (g_thr[lane + 64] < comb ? 1.f : 0.f) +
                (g_thr[lane + 96] < comb ? 1.f : 0.f);
    int i = (int)warpsum(cnt);
    const float4* U4 = (const float4*)(g_tabU + i * 128);
    const float4* V4 = (const float4*)(g_tabV + i * 128);
    float4 u = U4[lane], vv = V4[lane];
    float4 o;
    o.x = comb * u.x + vv.x;
    o.y = comb * u.y + vv.y;
    o.z = comb * u.z + vv.z;
    o.w = comb * u.w + vv.w;
    ((float4*)(out + (size_t)v * HH))[lane] = o;
}

// ============== persistent HMMA GEMM (R11): C = A @ W, W loaded ONCE =======
__global__ void __launch_bounds__(256, 2)
gemm_hmma(const float* __restrict__ A,
          const __nv_bfloat16* __restrict__ Wt,
          float* __restrict__ C) {
    extern __shared__ char smem[];
    uint32_t sb = smem_u32(smem);
    int tid = threadIdx.x;

    const uint4* Bh = (const uint4*)Wt;
    const uint4* Bl = (const uint4*)(Wt + 16384);
    #pragma unroll
    for (int i = tid; i < 2048; i += 256) {
        int n = i >> 4, kq = i & 15;
        uint32_t off = n * 272 + kq * 16;
        *(uint4*)(smem + B_HI + off) = Bh[i];
        *(uint4*)(smem + B_LO + off) = Bl[i];
    }

    int wid = tid >> 5, lane = tid & 31;
    int m0 = (wid & 1) * 32, n0 = (wid >> 1) * 32;
    int g = lane >> 3, r = lane & 7;
    uint32_t aoff0 = (uint32_t)((m0 + (g & 1) * 8 + r) * 272 + (g >> 1) * 16);
    uint32_t boff0 = (uint32_t)((n0 + (g >> 1) * 8 + r) * 272 + (g & 1) * 16);
    int cr = lane >> 2, cc = (lane & 3) * 2;

    for (int tile = blockIdx.x; tile < NTILES; tile += GEMM_GRID) {
        #pragma unroll
        for (int i = tid; i < 2048; i += 256) {
            int row = i >> 5, c4 = i & 31;
            float4 v = ((const float4*)(A + (size_t)tile * 64 * 128))[i];
            float f[4] = {v.x, v.y, v.z, v.w};
            union { uint2 u; __nv_bfloat16 h[4]; } ph, pl;
            #pragma unroll
            for (int e = 0; e < 4; e++) {
                __nv_bfloat16 hb = __float2bfloat16(f[e]);
                ph.h[e] = hb;
                pl.h[e] = __float2bfloat16(f[e] - __bfloat162float(hb));
            }
            uint32_t off = row * 272 + c4 * 8;
            *(uint2*)(smem + A_HI + off) = ph.u;
            *(uint2*)(smem + A_LO + off) = pl.u;
        }
        __syncthreads();

        float acc[2][4][4];
        #pragma unroll
        for (int a = 0; a < 2; a++)
            #pragma unroll
            for (int b = 0; b < 4; b++)
                #pragma unroll
                for (int c = 0; c < 4; c++) acc[a][b][c] = 0.f;

        #pragma unroll 4
        for (int k16 = 0; k16 < 8; k16++) {
            uint32_t ah[2][4], al[2][4], bh[4][2];
            ldsm_x4(ah[0], sb + A_HI + aoff0 + k16 * 32);
            ldsm_x4(ah[1], sb + A_HI + aoff0 + 16 * 272 + k16 * 32);
            ldsm_x4(al[0], sb + A_LO + aoff0 + k16 * 32);
            ldsm_x4(al[1], sb + A_LO + aoff0 + 16 * 272 + k16 * 32);
            ldsm_x4(&bh[0][0], sb + B_HI + boff0 + k16 * 32);
            ldsm_x4(&bh[2][0], sb + B_HI + boff0 + 16 * 272 + k16 * 32);
            #pragma unroll
            for (int mf = 0; mf < 2; mf++)
                #pragma unroll
                for (int nf = 0; nf < 4; nf++)
                    mma16816(acc[mf][nf], ah[mf], bh[nf]);
            #pragma unroll
            for (int mf = 0; mf < 2; mf++)
                #pragma unroll
                for (int nf = 0; nf < 4; nf++)
                    mma16816(acc[mf][nf], al[mf], bh[nf]);
        }
        #pragma unroll 4
        for (int k16 = 0; k16 < 8; k16++) {
            uint32_t ah[2][4], bl[4][2];
            ldsm_x4(ah[0], sb + A_HI + aoff0 + k16 * 32);
            ldsm_x4(ah[1], sb + A_HI + aoff0 + 16 * 272 + k16 * 32);
            ldsm_x4(&bl[0][0], sb + B_LO + boff0 + k16 * 32);
            ldsm_x4(&bl[2][0], sb + B_LO + boff0 + 16 * 272 + k16 * 32);
            #pragma unroll
            for (int mf = 0; mf < 2; mf++)
                #pragma unroll
                for (int nf = 0; nf < 4; nf++)
                    mma16816(acc[mf][nf], ah[mf], bl[nf]);
        }

        size_t rbase = (size_t)tile * 64;
        #pragma unroll
        for (int mf = 0; mf < 2; mf++) {
            #pragma unroll
            for (int nf = 0; nf < 4; nf++) {
                int col = n0 + nf * 8 + cc;
                int row0 = m0 + mf * 16 + cr;
                *(float2*)(C + (rbase + row0) * 128 + col) =
                    make_float2(acc[mf][nf][0], acc[mf][nf][1]);
                *(float2*)(C + (rbase + row0 + 8) * 128 + col) =
                    make_float2(acc[mf][nf][2], acc[mf][nf][3]);
            }
        }
        __syncthreads();
    }
}

// ====== fused lin+down chain (unchanged from R11) ==========================
__global__ void __launch_bounds__(512, 1)
gemm_fused2(const float* __restrict__ gC, const float* __restrict__ xup,
            const float* __restrict__ dbias,
            const __nv_bfloat16* __restrict__ Wt1, const float* __restrict__ lbias,
            const __nv_bfloat16* __restrict__ Wt2,
            float* __restrict__ out) {
    extern __shared__ char smem[];
    uint32_t sb = smem_u32(smem);
    int tid = threadIdx.x;

    {
        const uint4* B1h = (const uint4*)Wt1;
        const uint4* B1l = (const uint4*)(Wt1 + 16384);
        const uint4* B2h = (const uint4*)Wt2;
        const uint4* B2l = (const uint4*)(Wt2 + 16384);
        #pragma unroll
        for (int i = tid; i < 2048; i += 512) {
            int n = i >> 4, kq = i & 15;
            uint32_t off = n * 272 + kq * 16;
            *(uint4*)(smem + FB1_HI + off) = B1h[i];
            *(uint4*)(smem + FB1_LO + off) = B1l[i];
            *(uint4*)(smem + FB2_HI + off) = B2h[i];
            *(uint4*)(smem + FB2_LO + off) = B2l[i];
        }
    }

    int wid = tid >> 5, lane = tid & 31;
    int m0 = (wid & 3) * 32, n0 = (wid >> 2) * 32;
    int g = lane >> 3, r = lane & 7;
    uint32_t aoff0 = (uint32_t)((m0 + (g & 1) * 8 + r) * 272 + (g >> 1) * 16);
    uint32_t boff0 = (uint32_t)((n0 + (g >> 1) * 8 + r) * 272 + (g & 1) * 16);
    int cr = lane >> 2, cc = (lane & 3) * 2;

    for (int tile = blockIdx.x; tile < FTILES; tile += FGRID) {
        #pragma unroll
        for (int i = tid; i < 4096; i += 512) {
            int row = i >> 5, c4 = i & 31;
            int vv = tile * 128 + row;
            int l = vv & (LL - 1);
            float4 b4 = ((const float4*)dbias)[c4];
            float4 xu = ((const float4*)xup)[(size_t)vv * 32 + c4];
            float4 v;
            if (l == 0) {
                v.x = fmaxf(b4.x, 0.f) + xu.x;
                v.y = fmaxf(b4.y, 0.f) + xu.y;
                v.z = fmaxf(b4.z, 0.f) + xu.z;
                v.w = fmaxf(b4.w, 0.f) + xu.w;
            } else {
                int p = vv - l + ((l - 1) >> 1);
                float4 cp = ((const float4*)gC)[(size_t)p * 32 + c4];
                v.x = fmaxf(cp.x + b4.x, 0.f) + xu.x;
                v.y = fmaxf(cp.y + b4.y, 0.f) + xu.y;
                v.z = fmaxf(cp.z + b4.z, 0.f) + xu.z;
                v.w = fmaxf(cp.w + b4.w, 0.f) + xu.w;
            }
            float f[4] = {v.x, v.y, v.z, v.w};
            union { uint2 u; __nv_bfloat16 h[4]; } ph, pl;
            #pragma unroll
            for (int e = 0; e < 4; e++) {
                __nv_bfloat16 hb = __float2bfloat16(f[e]);
                ph.h[e] = hb;
                pl.h[e] = __float2bfloat16(f[e] - __bfloat162float(hb));
            }
            uint32_t off = row * 272 + c4 * 8;
            *(uint2*)(smem + FA_HI + off) = ph.u;
            *(uint2*)(smem + FA_LO + off) = pl.u;
        }
        __syncthreads();

        float acc[2][4][4];
        #pragma unroll
        for (int a = 0; a < 2; a++)
            #pragma unroll
            for (int b = 0; b < 4; b++)
                #pragma unroll
                for (int c = 0; c < 4; c++) acc[a][b][c] = 0.f;

        #pragma unroll 4
        for (int k16 = 0; k16 < 8; k16++) {
            uint32_t ah[2][4], al[2][4], bh[4][2];
            ldsm_x4(ah[0], sb + FA_HI + aoff0 + k16 * 32);
            ldsm_x4(ah[1], sb + FA_HI + aoff0 + 16 * 272 + k16 * 32);
            ldsm_x4(al[0], sb + FA_LO + aoff0 + k16 * 32);
            ldsm_x4(al[1], sb + FA_LO + aoff0 + 16 * 272 + k16 * 32);
            ldsm_x4(&bh[0][0], sb + FB1_HI + boff0 + k16 * 32);
            ldsm_x4(&bh[2][0], sb + FB1_HI + boff0 + 16 * 272 + k16 * 32);
            #pragma unroll
            for (int mf = 0; mf < 2; mf++)
                #pragma unroll
                for (int nf = 0; nf < 4; nf++)
                    mma16816(acc[mf][nf], ah[mf], bh[nf]);
            #pragma unroll
            for (int mf = 0; mf < 2; mf++)
                #pragma unroll
                for (int nf = 0; nf < 4; nf++)
                    mma16816(acc[mf][nf], al[mf], bh[nf]);
        }
        #pragma unroll 4
        for (int k16 = 0; k16 < 8; k16++) {
            uint32_t ah[2][4], bl[4][2];
            ldsm_x4(ah[0], sb + FA_HI + aoff0 + k16 * 32);
            ldsm_x4(ah[1], sb + FA_HI + aoff0 + 16 * 272 + k16 * 32);
            ldsm_x4(&bl[0][0], sb + FB1_LO + boff0 + k16 * 32);
            ldsm_x4(&bl[2][0], sb + FB1_LO + boff0 + 16 * 272 + k16 * 32);
            #pragma unroll
            for (int mf = 0; mf < 2; mf++)
                #pragma unroll
                for (int nf = 0; nf < 4; nf++)
                    mma16816(acc[mf][nf], ah[mf], bl[nf]);
        }
        __syncthreads();

        #pragma unroll
        for (int mf = 0; mf < 2; mf++) {
            #pragma unroll
            for (int nf = 0; nf < 4; nf++) {
                int col = n0 + nf * 8 + cc;
                float bx = lbias[col], by = lbias[col + 1];
                #pragma unroll
                for (int j = 0; j < 2; j++) {
                    int row = m0 + mf * 16 + cr + j * 8;
                    float f0 = fmaxf(acc[mf][nf][2 * j + 0] + bx, 0.f);
                    float f1 = fmaxf(acc[mf][nf][2 * j + 1] + by, 0.f);
                    union { uint32_t u; __nv_bfloat16 h[2]; } uh, ul;
                    uh.h[0] = __float2bfloat16(f0);
                    uh.h[1] = __float2bfloat16(f1);
                    ul.h[0] = __float2bfloat16(f0 - __bfloat162float(uh.h[0]));
                    ul.h[1] = __float2bfloat16(f1 - __bfloat162float(uh.h[1]));
                    uint32_t off = row * 272 + col * 2;
                    *(uint32_t*)(smem + FA_HI + off) = uh.u;
                    *(uint32_t*)(smem + FA_LO + off) = ul.u;
                }
            }
        }
        __syncthreads();

        #pragma unroll
        for (int a = 0; a < 2; a++)
            #pragma unroll
            for (int b = 0; b < 4; b++)
                #pragma unroll
                for (int c = 0; c < 4; c++) acc[a][b][c] = 0.f;

        #pragma unroll 4
        for (int k16 = 0; k16 < 8; k16++) {
            uint32_t ah[2][4], al[2][4], bh[4][2];
            ldsm_x4(ah[0], sb + FA_HI + aoff0 + k16 * 32);
            ldsm_x4(ah[1], sb + FA_HI + aoff0 + 16 * 272 + k16 * 32);
            ldsm_x4(al[0], sb + FA_LO + aoff0 + k16 * 32);
            ldsm_x4(al[1], sb + FA_LO + aoff0 + 16 * 272 + k16 * 32);
            ldsm_x4(&bh[0][0], sb + FB2_HI + boff0 + k16 * 32);
            ldsm_x4(&bh[2][0], sb + FB2_HI + boff0 + 16 * 272 + k16 * 32);
            #pragma unroll
            for (int mf = 0; mf < 2; mf++)
                #pragma unroll
                for (int nf = 0; nf < 4; nf++)
                    mma16816(acc[mf][nf], ah[mf], bh[nf]);
            #pragma unroll
            for (int mf = 0; mf < 2; mf++)
                #pragma unroll
                for (int nf = 0; nf < 4; nf++)
                    mma16816(acc[mf][nf], al[mf], bh[nf]);
        }
        #pragma unroll 4
        for (int k16 = 0; k16 < 8; k16++) {
            uint32_t ah[2][4], bl[4][2];
            ldsm_x4(ah[0], sb + FA_HI + aoff0 + k16 * 32);
            ldsm_x4(ah[1], sb + FA_HI + aoff0 + 16 * 272 + k16 * 32);
            ldsm_x4(&bl[0][0], sb + FB2_LO + boff0 + k16 * 32);
            ldsm_x4(&bl[2][0], sb + FB2_LO + boff0 + 16 * 272 + k16 * 32);
            #pragma unroll
            for (int mf = 0; mf < 2; mf++)
                #pragma unroll
                for (int nf = 0; nf < 4; nf++)
                    mma16816(acc[mf][nf], ah[mf], bl[nf]);
        }

        size_t rbase = (size_t)tile * 128;
        #pragma unroll
        for (int mf = 0; mf < 2; mf++) {
            #pragma unroll
            for (int nf = 0; nf < 4; nf++) {
                int col = n0 + nf * 8 + cc;
                int row0 = m0 + mf * 16 + cr;
                *(float2*)(out + (rbase + row0) * 128 + col) =
                    make_float2(acc[mf][nf][0], acc[mf][nf][1]);
                *(float2*)(out + (rbase + row0 + 8) * 128 + col) =
                    make_float2(acc[mf][nf][2], acc[mf][nf][3]);
            }
        }
        __syncthreads();
    }
}

// ---------------- tiny precompute: w_e = We @ a_e per up layer, W0 dots ----
__global__ void precompute_k(const float* __restrict__ up_We,
                             const float* __restrict__ up_ae,
                             const float* __restrict__ up_W0,
                             const float* __restrict__ as0,
                             const float* __restrict__ ad0) {
    int lane = threadIdx.x;
    for (int i = 0; i < 3; i++) {
        for (int d = 0; d < 4; d++) {
            float s = 0.f;
            for (int t = lane; t < HH; t += 32)
                s += up_We[(i * 4 + d) * HH + t] * up_ae[i * HH + t];
            s = warpsum(s);
            if (lane == 0) g_pre[i * 4 + d] = s;
        }
    }
    float s = 0.f;
    for (int t = lane; t < HH; t += 32) s += up_W0[t] * as0[t];
    s = warpsum(s);
    if (lane == 0) g_pre[12] = s;
    s = 0.f;
    for (int t = lane; t < HH; t += 32) s += up_W0[t] * ad0[t];
    s = warpsum(s);
    if (lane == 0) g_pre[13] = s;
}

// ---------------- up attention (standalone): warp per node -----------------
__global__ void up_attn_k(const float* __restrict__ h, const float* __restrict__ a_s,
                          const float* __restrict__ a_d,
                          const float* __restrict__ edge_attr, int layer,
                          const float* __restrict__ bias, float* __restrict__ out) {
    int w = threadIdx.x >> 5, lane = threadIdx.x & 31;
    int v = blockIdx.x * 8 + w;
    int l = v & (LL - 1), bi = v >> LOG2L;
    const float4* H = (const float4*)h;
    float4 hv = H[(size_t)v * 32 + lane];
    float4 b4 = ((const float4*)bias)[lane];
    int nc = (l < 1023) ? 2 : ((l == 1023) ? 1 : 0);
    float4* O = (float4*)(out + (size_t)v * HH);
    if (nc == 0) {
        float4 o;
        o.x = fmaxf(hv.x + b4.x, 0.f); o.y = fmaxf(hv.y + b4.y, 0.f);
        o.z = fmaxf(hv.z + b4.z, 0.f); o.w = fmaxf(hv.w + b4.w, 0.f);
        O[lane] = o;
        return;
    }
    int c1 = v + l + 1;
    float4 h1 = H[(size_t)c1 * 32 + lane];
    float4 h2 = (nc == 2) ? H[(size_t)(c1 + 1) * 32 + lane] : make_float4(0, 0, 0, 0);
    float4 as4 = ((const float4*)a_s)[lane];
    float4 ad4 = ((const float4*)a_d)[lane];
    float A1 = warpsum(dot4(h1, as4));
    float A2 = warpsum(dot4(h2, as4));
    float AV = warpsum(dot4(hv, as4));
    float DV = warpsum(dot4(hv, ad4));

    const float* we = g_pre + layer * 4;
    long e1 = (long)bi * 2047 + 2 * l;
    const float* ea1 = edge_attr + e1 * 4;
    float e1s = ea1[0] * we[0] + ea1[1] * we[1] + ea1[2] * we[2] + ea1[3] * we[3];
    float e2s = 0.f;
    if (nc == 2) {
        const float* ea2 = ea1 + 4;
        e2s = ea2[0] * we[0] + ea2[1] * we[1] + ea2[2] * we[2] + ea2[3] * we[3];
    }
    float s1 = lrelu(A1 + DV + e1s);
    float s2 = (nc == 2) ? lrelu(A2 + DV + e2s) : -1e30f;
    float emean = (nc == 2) ? 0.5f * (e1s + e2s) : e1s;
    float ss = lrelu(AV + DV + emean);
    float m = fmaxf(ss, fmaxf(s1, s2));
    float w1 = __expf(s1 - m);
    float w2 = (nc == 2) ? __expf(s2 - m) : 0.f;
    float ws = __expf(ss - m);
    float inv = 1.f / (w1 + w2 + ws);
    float4 o;
    o.x = fmaxf((w1 * h1.x + w2 * h2.x + ws * hv.x) * inv + b4.x, 0.f);
    o.y = fmaxf((w1 * h1.y + w2 * h2.y + ws * hv.y) * inv + b4.y, 0.f);
    o.z = fmaxf((w1 * h1.z + w2 * h2.z + ws * hv.z) * inv + b4.z, 0.f);
    o.w = fmaxf((w1 * h1.w + w2 * h2.w + ws * hv.w) * inv + b4.w, 0.f);
    O[lane] = o;
}

// ------- last down_attn fused with final dot: warp per node ---------------
__global__ void down_final_k(const float* __restrict__ h, const float* __restrict__ bias,
                             const float* __restrict__ x_up, const float* __restrict__ wlast,
                             float* __restrict__ emb, float* __restrict__ dotv) {
    int w = threadIdx.x >> 5, lane = threadIdx.x & 31;
    int v = blockIdx.x * 8 + w;
    int l = v & (LL - 1);
    float4 xu = ((const float4*)x_up)[(size_t)v * 32 + lane];
    float4 b4 = ((const float4*)bias)[lane];
    float4 val;
    if (l == 0) val = b4;
    else {
        int p = v - l + ((l - 1) >> 1);
        float4 hp = ((const float4*)h)[(size_t)p * 32 + lane];
        val.x = hp.x + b4.x; val.y = hp.y + b4.y;
        val.z = hp.z + b4.z; val.w = hp.w + b4.w;
    }
    float4 o;
    o.x = fmaxf(val.x, 0.f) + xu.x;
    o.y = fmaxf(val.y, 0.f) + xu.y;
    o.z = fmaxf(val.z, 0.f) + xu.z;
    o.w = fmaxf(val.w, 0.f) + xu.w;
    ((float4*)(emb + (size_t)v * HH))[lane] = o;
    float4 w4 = ((const float4*)wlast)[lane];
    float q = warpsum(dot4(o, w4));
    if (lane == 0) dotv[v] = q;
}

// ---------------- out[v] = dotv[v] - dotv[root(v)] -------------------------
__global__ void sub_k(const float* __restrict__ dotv, float* __restrict__ out) {
    int v = blockIdx.x * 256 + threadIdx.x;
    out[v] = dotv[v] - dotv[v & ~(LL - 1)];
}

// ---------------------------------------------------------------------------
extern "C" void kernel_launch(void* const* d_in, const int* in_sizes, int n_in,
                              void* d_out, int out_size) {
    const float* x         = (const float*)d_in[0];
    const float* edge_attr = (const float*)d_in[3];
    const float* up_W0     = (const float*)d_in[4];
    const float* up_W      = (const float*)d_in[5];
    const float* up_as     = (const float*)d_in[6];
    const float* up_ad     = (const float*)d_in[7];
    const float* up_We     = (const float*)d_in[8];
    const float* up_ae     = (const float*)d_in[9];
    const float* up_b      = (const float*)d_in[10];
    const float* down_W    = (const float*)d_in[11];
    const float* down_b    = (const float*)d_in[16];
    const float* lin_W     = (const float*)d_in[17];
    const float* lin_b     = (const float*)d_in[18];
    const float* lin_lW    = (const float*)d_in[19];

    float *bufA, *bufB, *bufC, *bufD;
    __nv_bfloat16* wt;
    cudaGetSymbolAddress((void**)&bufA, g_bufA);
    cudaGetSymbolAddress((void**)&bufB, g_bufB);
    cudaGetSymbolAddress((void**)&bufC, g_bufC);
    cudaGetSymbolAddress((void**)&bufD, g_bufD);
    cudaGetSymbolAddress((void**)&wt, g_wt);

    cudaFuncSetAttribute(gemm_hmma, cudaFuncAttributeMaxDynamicSharedMemorySize,
                         SMEM_GEMM);
    cudaFuncSetAttribute(gemm_fused2, cudaFuncAttributeMaxDynamicSharedMemorySize,
                         SMEM_FUSED);

    float* out = (float*)d_out;
    float* emb = out + NN;   // output tuple: (out[B*L], emb[B*L*H]) concatenated

    // mats: 0,1 = up_W[0..1]; 2,3 = down_W[0..1]; 4,5 = lin_W[0..1]
    #define WT(m) (wt + (m) * 2 * 16384)

    precompute_k<<<1, 32>>>(up_We, up_ae, up_W0, up_as, up_ad);
    precompute2_k<<<1, 128>>>(up_W0, up_b, up_W);
    wconv_k<<<768, 128>>>(up_W, down_W, lin_W);

    // --- layers 0+1 GEMM collapsed: C1 = relu(comb*W0+b0) @ up_W1 via
    //     piecewise-linear table (exact fp32) ---
    layer1_k<<<NN / 8, 256>>>(x, edge_attr, bufC);
    up_attn_k<<<NN / 8, 256>>>(bufC, up_as + HH, up_ad + HH, edge_attr, 1, up_b + HH, bufB);

    // --- up layer 2 -> x_up (bufA) ---
    gemm_hmma<<<GEMM_GRID, 256, SMEM_GEMM>>>(bufB, WT(1), bufC);
    up_attn_k<<<NN / 8, 256>>>(bufC, up_as + 2 * HH, up_ad + 2 * HH, edge_attr, 2,
                               up_b + 2 * HH, bufA);

    // --- down 0 GEMM: C0 = x_up @ down_W0 ---
    gemm_hmma<<<GEMM_GRID, 256, SMEM_GEMM>>>(bufA, WT(2), bufC);

    // --- loop i=0 fused: bufD = [relu(gather(bufC))+xup] @linW0 relu @downW0
    gemm_fused2<<<FGRID, 512, SMEM_FUSED>>>(bufC, bufA, down_b,
                                            WT(4), lin_b, WT(2), bufD);
    // --- loop i=1 fused: bufC = [relu(gather(bufD))+xup] @linW1 relu @downW1
    gemm_fused2<<<FGRID, 512, SMEM_FUSED>>>(bufD, bufA, down_b,
                                            WT(5), lin_b + HH, WT(3), bufC);

    // --- last down_attn fused with final dot (emb into d_out, dotv in bufB) ---
    down_final_k<<<NN / 8, 256>>>(bufC, down_b + HH, bufA, lin_lW, emb, bufB);

    // --- out[v] = dotv[v] - dotv[root] ---
    sub_k<<<NN / 256, 256>>>(bufB, out);
}

// round 15
// speedup vs baseline: 1.1180x; 1.0466x over previous
#include <cuda_runtime.h>
#include <cuda_bf16.h>
#include <cstdint>

#define NN 131072      // B*L nodes
#define LL 2048        // nodes per tree
#define HH 128         // hidden
#define LOG2L 11
#define GEMM_GRID 296  // 2 CTAs per SM x 148 SMs, persistent
#define NTILES 2048    // NN / 64
#define FTILES 1024    // NN / 128 (fused kernel, 128-row tiles)
#define FGRID 148

// ---------------- scratch (device globals; no allocation allowed) ----------
__device__ float g_bufA[NN * HH];   // x_up
__device__ float g_bufB[NN * HH];   // layer cur / dotv buffer
__device__ float g_bufC[NN * HH];   // gemm out
__device__ float g_bufD[NN * HH];   // fused chain ping-pong
__device__ float g_pre[16];         // [0..11] w_e per up layer, [12]=W0·a_s, [13]=W0·a_d
__device__ float g_thr[128];        // sorted relu breakpoints for layer0+gemm1
__device__ int   g_ord[128];        // permutation: sorted idx -> original j
__device__ float g_tabU[129 * 128]; // per-interval affine slope table
__device__ float g_tabV[129 * 128]; // per-interval affine offset table
__device__ __nv_bfloat16 g_wt[12 * 16384];  // 6 mats x {hi,lo} planes, transposed [n][k]

__device__ __forceinline__ float lrelu(float v) { return v > 0.f ? v : 0.2f * v; }
__device__ __forceinline__ float warpsum(float v) {
    #pragma unroll
    for (int o = 16; o; o >>= 1) v += __shfl_xor_sync(0xffffffffu, v, o);
    return v;
}
__device__ __forceinline__ float dot4(float4 a, float4 b) {
    return a.x * b.x + a.y * b.y + a.z * b.z + a.w * b.w;
}
__device__ __forceinline__ uint32_t smem_u32(const void* p) {
    uint32_t a;
    asm("{ .reg .u64 t; cvta.to.shared.u64 t, %1; cvt.u32.u64 %0, t; }" : "=r"(a) : "l"(p));
    return a;
}

// ======================= HMMA helpers (sm_80+ PTX) =========================
__device__ __forceinline__ void ldsm_x4(uint32_t* r, uint32_t addr) {
    asm volatile("ldmatrix.sync.aligned.m8n8.x4.shared.b16 {%0,%1,%2,%3}, [%4];"
                 : "=r"(r[0]), "=r"(r[1]), "=r"(r[2]), "=r"(r[3]) : "r"(addr));
}
__device__ __forceinline__ void mma16816(float* c, const uint32_t* a, const uint32_t* b) {
    asm volatile("mma.sync.aligned.m16n8k16.row.col.f32.bf16.bf16.f32 "
                 "{%0,%1,%2,%3}, {%4,%5,%6,%7}, {%8,%9}, {%0,%1,%2,%3};"
                 : "+f"(c[0]), "+f"(c[1]), "+f"(c[2]), "+f"(c[3])
                 : "r"(a[0]), "r"(a[1]), "r"(a[2]), "r"(a[3]), "r"(b[0]), "r"(b[1]));
}

// SMEM layout, plain GEMM (row stride 272 B)
#define A_HI 0
#define A_LO 17408
#define B_HI 34816
#define B_LO 69632
#define SMEM_GEMM 104448
// SMEM layout, fused kernel (128-row A, two B matrices)
#define FA_HI 0
#define FA_LO 34816
#define FB1_HI 69632
#define FB1_LO 104448
#define FB2_HI 139264
#define FB2_LO 174080
#define SMEM_FUSED 208896

// ---------------- weight pre-conversion: W[k][n] -> hi/lo bf16 [n][k] ------
__global__ void wconv_k(const float* __restrict__ up_W,
                        const float* __restrict__ down_W,
                        const float* __restrict__ lin_W) {
    int bx = blockIdx.x;
    int mat = bx >> 7, n = bx & 127, k = threadIdx.x;
    const float* W = (mat < 2) ? up_W + mat * 16384
                   : (mat < 4) ? down_W + (mat - 2) * 16384
                               : lin_W + (mat - 4) * 16384;
    float w = W[k * 128 + n];
    __nv_bfloat16 hb = __float2bfloat16(w);
    float hf = __bfloat162float(hb);
    g_wt[(mat * 2 + 0) * 16384 + n * 128 + k] = hb;
    g_wt[(mat * 2 + 1) * 16384 + n * 128 + k] = __float2bfloat16(w - hf);
}

// ---- rank_k: sort relu breakpoints t_j = -b/W0 (1 small block, smem only) -
__global__ void rank_k(const float* __restrict__ W0, const float* __restrict__ ub) {
    __shared__ float t[128];
    int j = threadIdx.x;
    float w0 = W0[j], b = ub[j];
    float tj = (w0 != 0.f) ? (-b / w0) : 3.0e38f;
    t[j] = tj;
    __syncthreads();
    int rank = 0;
    for (int k = 0; k < 128; k++) {
        float tk = t[k];
        if (tk < tj || (tk == tj && k < j)) rank++;
    }
    g_thr[rank] = tj;
    g_ord[rank] = j;
}

// ---- table_k: interval i row of (U,V); 129 blocks x 128 threads (parallel)
// active_j(i) = (w0>0 && m<i) || (w0<0 && m>=i) || (w0==0 && b>0), m=sorted pos
__global__ void table_k(const float* __restrict__ W0, const float* __restrict__ ub,
                        const float* __restrict__ W1) {
    __shared__ float w0s[128], bs[128];
    __shared__ int ords[128];
    int n = threadIdx.x, i = blockIdx.x;
    w0s[n] = W0[n]; bs[n] = ub[n]; ords[n] = g_ord[n];
    __syncthreads();
    float U = 0.f, V = 0.f;
    #pragma unroll 4
    for (int m = 0; m < 128; m++) {
        int j = ords[m];
        float w0 = w0s[j], b = bs[j];
        float w1 = W1[j * 128 + n];
        bool act = (w0 > 0.f && m < i) || (w0 < 0.f && m >= i) ||
                   (w0 == 0.f && b > 0.f);
        if (act) { U += w0 * w1; V += b * w1; }
    }
    g_tabU[i * 128 + n] = U;
    g_tabV[i * 128 + n] = V;
}

// ---- layer1_k: C1[v,:] = comb(v)*U_i + V_i  (replaces up0_k + gemm1) ------
__global__ void layer1_k(const float* __restrict__ x,
                         const float* __restrict__ edge_attr,
                         float* __restrict__ out) {
    int w = threadIdx.x >> 5, lane = threadIdx.x & 31;
    int v = blockIdx.x * 8 + w;
    int l = v & (LL - 1), bi = v >> LOG2L;
    float xv = x[v];
    int nc = (l < 1023) ? 2 : ((l == 1023) ? 1 : 0);
    float comb;
    if (nc == 0) {
        comb = xv;
    } else {
        float was = g_pre[12], wad = g_pre[13];
        int c1 = v + l + 1;
        float x1 = x[c1];
        float x2 = (nc == 2) ? x[c1 + 1] : 0.f;
        long e1 = (long)bi * 2047 + 2 * l;
        const float* ea1 = edge_attr + e1 * 4;
        float e1s = ea1[0] * g_pre[0] + ea1[1] * g_pre[1] +
                    ea1[2] * g_pre[2] + ea1[3] * g_pre[3];
        float e2s = 0.f;
        if (nc == 2) {
            const float* ea2 = ea1 + 4;
            e2s = ea2[0] * g_pre[0] + ea2[1] * g_pre[1] +
                  ea2[2] * g_pre[2] + ea2[3] * g_pre[3];
        }
        float adv = xv * wad;
        float s1 = lrelu(x1 * was + adv + e1s);
        float s2 = (nc == 2) ? lrelu(x2 * was + adv + e2s) : -1e30f;
        float emean = (nc == 2) ? 0.5f * (e1s + e2s) : e1s;
        float ss = lrelu(xv * was + adv + emean);
        float m = fmaxf(ss, fmaxf(s1, s2));
        float w1 = __expf(s1 - m);
        float w2 = (nc == 2) ? __expf(s2 - m) : 0.f;
        float ws = __expf(ss - m);
        comb = (w1 * x1 + w2 * x2 + ws * xv) / (w1 + w2 + ws);
    }
    // interval index: count of sorted thresholds below comb
    float cnt = (g_thr[lane] < comb ? 1.f : 0.f) +
                (g_thr[lane + 32] < comb ? 1.f : 0.f) +
                (g_thr[lane + 64] < comb ? 1.f : 0.f) +
                (g_thr[lane + 96] < comb ? 1.f : 0.f);
    int i = (int)warpsum(cnt);
    const float4* U4 = (const float4*)(g_tabU + i * 128);
    const float4* V4 = (const float4*)(g_tabV + i * 128);
    float4 u = U4[lane], vv = V4[lane];
    float4 o;
    o.x = comb * u.x + vv.x;
    o.y = comb * u.y + vv.y;
    o.z = comb * u.z + vv.z;
    o.w = comb * u.w + vv.w;
    ((float4*)(out + (size_t)v * HH))[lane] = o;
}

// ============== persistent HMMA GEMM (R11): C = A @ W, W loaded ONCE =======
__global__ void __launch_bounds__(256, 2)
gemm_hmma(const float* __restrict__ A,
          const __nv_bfloat16* __restrict__ Wt,
          float* __restrict__ C) {
    extern __shared__ char smem[];
    uint32_t sb = smem_u32(smem);
    int tid = threadIdx.x;

    const uint4* Bh = (const uint4*)Wt;
    const uint4* Bl = (const uint4*)(Wt + 16384);
    #pragma unroll
    for (int i = tid; i < 2048; i += 256) {
        int n = i >> 4, kq = i & 15;
        uint32_t off = n * 272 + kq * 16;
        *(uint4*)(smem + B_HI + off) = Bh[i];
        *(uint4*)(smem + B_LO + off) = Bl[i];
    }

    int wid = tid >> 5, lane = tid & 31;
    int m0 = (wid & 1) * 32, n0 = (wid >> 1) * 32;
    int g = lane >> 3, r = lane & 7;
    uint32_t aoff0 = (uint32_t)((m0 + (g & 1) * 8 + r) * 272 + (g >> 1) * 16);
    uint32_t boff0 = (uint32_t)((n0 + (g >> 1) * 8 + r) * 272 + (g & 1) * 16);
    int cr = lane >> 2, cc = (lane & 3) * 2;

    for (int tile = blockIdx.x; tile < NTILES; tile += GEMM_GRID) {
        #pragma unroll
        for (int i = tid; i < 2048; i += 256) {
            int row = i >> 5, c4 = i & 31;
            float4 v = ((const float4*)(A + (size_t)tile * 64 * 128))[i];
            float f[4] = {v.x, v.y, v.z, v.w};
            union { uint2 u; __nv_bfloat16 h[4]; } ph, pl;
            #pragma unroll
            for (int e = 0; e < 4; e++) {
                __nv_bfloat16 hb = __float2bfloat16(f[e]);
                ph.h[e] = hb;
                pl.h[e] = __float2bfloat16(f[e] - __bfloat162float(hb));
            }
            uint32_t off = row * 272 + c4 * 8;
            *(uint2*)(smem + A_HI + off) = ph.u;
            *(uint2*)(smem + A_LO + off) = pl.u;
        }
        __syncthreads();

        float acc[2][4][4];
        #pragma unroll
        for (int a = 0; a < 2; a++)
            #pragma unroll
            for (int b = 0; b < 4; b++)
                #pragma unroll
                for (int c = 0; c < 4; c++) acc[a][b][c] = 0.f;

        #pragma unroll 4
        for (int k16 = 0; k16 < 8; k16++) {
            uint32_t ah[2][4], al[2][4], bh[4][2];
            ldsm_x4(ah[0], sb + A_HI + aoff0 + k16 * 32);
            ldsm_x4(ah[1], sb + A_HI + aoff0 + 16 * 272 + k16 * 32);
            ldsm_x4(al[0], sb + A_LO + aoff0 + k16 * 32);
            ldsm_x4(al[1], sb + A_LO + aoff0 + 16 * 272 + k16 * 32);
            ldsm_x4(&bh[0][0], sb + B_HI + boff0 + k16 * 32);
            ldsm_x4(&bh[2][0], sb + B_HI + boff0 + 16 * 272 + k16 * 32);
            #pragma unroll
            for (int mf = 0; mf < 2; mf++)
                #pragma unroll
                for (int nf = 0; nf < 4; nf++)
                    mma16816(acc[mf][nf], ah[mf], bh[nf]);
            #pragma unroll
            for (int mf = 0; mf < 2; mf++)
                #pragma unroll
                for (int nf = 0; nf < 4; nf++)
                    mma16816(acc[mf][nf], al[mf], bh[nf]);
        }
        #pragma unroll 4
        for (int k16 = 0; k16 < 8; k16++) {
            uint32_t ah[2][4], bl[4][2];
            ldsm_x4(ah[0], sb + A_HI + aoff0 + k16 * 32);
            ldsm_x4(ah[1], sb + A_HI + aoff0 + 16 * 272 + k16 * 32);
            ldsm_x4(&bl[0][0], sb + B_LO + boff0 + k16 * 32);
            ldsm_x4(&bl[2][0], sb + B_LO + boff0 + 16 * 272 + k16 * 32);
            #pragma unroll
            for (int mf = 0; mf < 2; mf++)
                #pragma unroll
                for (int nf = 0; nf < 4; nf++)
                    mma16816(acc[mf][nf], ah[mf], bl[nf]);
        }

        size_t rbase = (size_t)tile * 64;
        #pragma unroll
        for (int mf = 0; mf < 2; mf++) {
            #pragma unroll
            for (int nf = 0; nf < 4; nf++) {
                int col = n0 + nf * 8 + cc;
                int row0 = m0 + mf * 16 + cr;
                *(float2*)(C + (rbase + row0) * 128 + col) =
                    make_float2(acc[mf][nf][0], acc[mf][nf][1]);
                *(float2*)(C + (rbase + row0 + 8) * 128 + col) =
                    make_float2(acc[mf][nf][2], acc[mf][nf][3]);
            }
        }
        __syncthreads();
    }
}

// ====== fused lin+down chain (unchanged from R11) ==========================
__global__ void __launch_bounds__(512, 1)
gemm_fused2(const float* __restrict__ gC, const float* __restrict__ xup,
            const float* __restrict__ dbias,
            const __nv_bfloat16* __restrict__ Wt1, const float* __restrict__ lbias,
            const __nv_bfloat16* __restrict__ Wt2,
            float* __restrict__ out) {
    extern __shared__ char smem[];
    uint32_t sb = smem_u32(smem);
    int tid = threadIdx.x;

    {
        const uint4* B1h = (const uint4*)Wt1;
        const uint4* B1l = (const uint4*)(Wt1 + 16384);
        const uint4* B2h = (const uint4*)Wt2;
        const uint4* B2l = (const uint4*)(Wt2 + 16384);
        #pragma unroll
        for (int i = tid; i < 2048; i += 512) {
            int n = i >> 4, kq = i & 15;
            uint32_t off = n * 272 + kq * 16;
            *(uint4*)(smem + FB1_HI + off) = B1h[i];
            *(uint4*)(smem + FB1_LO + off) = B1l[i];
            *(uint4*)(smem + FB2_HI + off) = B2h[i];
            *(uint4*)(smem + FB2_LO + off) = B2l[i];
        }
    }

    int wid = tid >> 5, lane = tid & 31;
    int m0 = (wid & 3) * 32, n0 = (wid >> 2) * 32;
    int g = lane >> 3, r = lane & 7;
    uint32_t aoff0 = (uint32_t)((m0 + (g & 1) * 8 + r) * 272 + (g >> 1) * 16);
    uint32_t boff0 = (uint32_t)((n0 + (g >> 1) * 8 + r) * 272 + (g & 1) * 16);
    int cr = lane >> 2, cc = (lane & 3) * 2;

    for (int tile = blockIdx.x; tile < FTILES; tile += FGRID) {
        #pragma unroll
        for (int i = tid; i < 4096; i += 512) {
            int row = i >> 5, c4 = i & 31;
            int vv = tile * 128 + row;
            int l = vv & (LL - 1);
            float4 b4 = ((const float4*)dbias)[c4];
            float4 xu = ((const float4*)xup)[(size_t)vv * 32 + c4];
            float4 v;
            if (l == 0) {
                v.x = fmaxf(b4.x, 0.f) + xu.x;
                v.y = fmaxf(b4.y, 0.f) + xu.y;
                v.z = fmaxf(b4.z, 0.f) + xu.z;
                v.w = fmaxf(b4.w, 0.f) + xu.w;
            } else {
                int p = vv - l + ((l - 1) >> 1);
                float4 cp = ((const float4*)gC)[(size_t)p * 32 + c4];
                v.x = fmaxf(cp.x + b4.x, 0.f) + xu.x;
                v.y = fmaxf(cp.y + b4.y, 0.f) + xu.y;
                v.z = fmaxf(cp.z + b4.z, 0.f) + xu.z;
                v.w = fmaxf(cp.w + b4.w, 0.f) + xu.w;
            }
            float f[4] = {v.x, v.y, v.z, v.w};
            union { uint2 u; __nv_bfloat16 h[4]; } ph, pl;
            #pragma unroll
            for (int e = 0; e < 4; e++) {
                __nv_bfloat16 hb = __float2bfloat16(f[e]);
                ph.h[e] = hb;
                pl.h[e] = __float2bfloat16(f[e] - __bfloat162float(hb));
            }
            uint32_t off = row * 272 + c4 * 8;
            *(uint2*)(smem + FA_HI + off) = ph.u;
            *(uint2*)(smem + FA_LO + off) = pl.u;
        }
        __syncthreads();

        float acc[2][4][4];
        #pragma unroll
        for (int a = 0; a < 2; a++)
            #pragma unroll
            for (int b = 0; b < 4; b++)
                #pragma unroll
                for (int c = 0; c < 4; c++) acc[a][b][c] = 0.f;

        #pragma unroll 4
        for (int k16 = 0; k16 < 8; k16++) {
            uint32_t ah[2][4], al[2][4], bh[4][2];
            ldsm_x4(ah[0], sb + FA_HI + aoff0 + k16 * 32);
            ldsm_x4(ah[1], sb + FA_HI + aoff0 + 16 * 272 + k16 * 32);
            ldsm_x4(al[0], sb + FA_LO + aoff0 + k16 * 32);
            ldsm_x4(al[1], sb + FA_LO + aoff0 + 16 * 272 + k16 * 32);
            ldsm_x4(&bh[0][0], sb + FB1_HI + boff0 + k16 * 32);
            ldsm_x4(&bh[2][0], sb + FB1_HI + boff0 + 16 * 272 + k16 * 32);
            #pragma unroll
            for (int mf = 0; mf < 2; mf++)
                #pragma unroll
                for (int nf = 0; nf < 4; nf++)
                    mma16816(acc[mf][nf], ah[mf], bh[nf]);
            #pragma unroll
            for (int mf = 0; mf < 2; mf++)
                #pragma unroll
                for (int nf = 0; nf < 4; nf++)
                    mma16816(acc[mf][nf], al[mf], bh[nf]);
        }
        #pragma unroll 4
        for (int k16 = 0; k16 < 8; k16++) {
            uint32_t ah[2][4], bl[4][2];
            ldsm_x4(ah[0], sb + FA_HI + aoff0 + k16 * 32);
            ldsm_x4(ah[1], sb + FA_HI + aoff0 + 16 * 272 + k16 * 32);
            ldsm_x4(&bl[0][0], sb + FB1_LO + boff0 + k16 * 32);
            ldsm_x4(&bl[2][0], sb + FB1_LO + boff0 + 16 * 272 + k16 * 32);
            #pragma unroll
            for (int mf = 0; mf < 2; mf++)
                #pragma unroll
                for (int nf = 0; nf < 4; nf++)
                    mma16816(acc[mf][nf], ah[mf], bl[nf]);
        }
        __syncthreads();

        #pragma unroll
        for (int mf = 0; mf < 2; mf++) {
            #pragma unroll
            for (int nf = 0; nf < 4; nf++) {
                int col = n0 + nf * 8 + cc;
                float bx = lbias[col], by = lbias[col + 1];
                #pragma unroll
                for (int j = 0; j < 2; j++) {
                    int row = m0 + mf * 16 + cr + j * 8;
                    float f0 = fmaxf(acc[mf][nf][2 * j + 0] + bx, 0.f);
                    float f1 = fmaxf(acc[mf][nf][2 * j + 1] + by, 0.f);
                    union { uint32_t u; __nv_bfloat16 h[2]; } uh, ul;
                    uh.h[0] = __float2bfloat16(f0);
                    uh.h[1] = __float2bfloat16(f1);
                    ul.h[0] = __float2bfloat16(f0 - __bfloat162float(uh.h[0]));
                    ul.h[1] = __float2bfloat16(f1 - __bfloat162float(uh.h[1]));
                    uint32_t off = row * 272 + col * 2;
                    *(uint32_t*)(smem + FA_HI + off) = uh.u;
                    *(uint32_t*)(smem + FA_LO + off) = ul.u;
                }
            }
        }
        __syncthreads();

        #pragma unroll
        for (int a = 0; a < 2; a++)
            #pragma unroll
            for (int b = 0; b < 4; b++)
                #pragma unroll
                for (int c = 0; c < 4; c++) acc[a][b][c] = 0.f;

        #pragma unroll 4
        for (int k16 = 0; k16 < 8; k16++) {
            uint32_t ah[2][4], al[2][4], bh[4][2];
            ldsm_x4(ah[0], sb + FA_HI + aoff0 + k16 * 32);
            ldsm_x4(ah[1], sb + FA_HI + aoff0 + 16 * 272 + k16 * 32);
            ldsm_x4(al[0], sb + FA_LO + aoff0 + k16 * 32);
            ldsm_x4(al[1], sb + FA_LO + aoff0 + 16 * 272 + k16 * 32);
            ldsm_x4(&bh[0][0], sb + FB2_HI + boff0 + k16 * 32);
            ldsm_x4(&bh[2][0], sb + FB2_HI + boff0 + 16 * 272 + k16 * 32);
            #pragma unroll
            for (int mf = 0; mf < 2; mf++)
                #pragma unroll
                for (int nf = 0; nf < 4; nf++)
                    mma16816(acc[mf][nf], ah[mf], bh[nf]);
            #pragma unroll
            for (int mf = 0; mf < 2; mf++)
                #pragma unroll
                for (int nf = 0; nf < 4; nf++)
                    mma16816(acc[mf][nf], al[mf], bh[nf]);
        }
        #pragma unroll 4
        for (int k16 = 0; k16 < 8; k16++) {
            uint32_t ah[2][4], bl[4][2];
            ldsm_x4(ah[0], sb + FA_HI + aoff0 + k16 * 32);
            ldsm_x4(ah[1], sb + FA_HI + aoff0 + 16 * 272 + k16 * 32);
            ldsm_x4(&bl[0][0], sb + FB2_LO + boff0 + k16 * 32);
            ldsm_x4(&bl[2][0], sb + FB2_LO + boff0 + 16 * 272 + k16 * 32);
            #pragma unroll
            for (int mf = 0; mf < 2; mf++)
                #pragma unroll
                for (int nf = 0; nf < 4; nf++)
                    mma16816(acc[mf][nf], ah[mf], bl[nf]);
        }

        size_t rbase = (size_t)tile * 128;
        #pragma unroll
        for (int mf = 0; mf < 2; mf++) {
            #pragma unroll
            for (int nf = 0; nf < 4; nf++) {
                int col = n0 + nf * 8 + cc;
                int row0 = m0 + mf * 16 + cr;
                *(float2*)(out + (rbase + row0) * 128 + col) =
                    make_float2(acc[mf][nf][0], acc[mf][nf][1]);
                *(float2*)(out + (rbase + row0 + 8) * 128 + col) =
                    make_float2(acc[mf][nf][2], acc[mf][nf][3]);
            }
        }
        __syncthreads();
    }
}

// ---------------- tiny precompute: w_e = We @ a_e per up layer, W0 dots ----
__global__ void precompute_k(const float* __restrict__ up_We,
                             const float* __restrict__ up_ae,
                             const float* __restrict__ up_W0,
                             const float* __restrict__ as0,
                             const float* __restrict__ ad0) {
    int lane = threadIdx.x;
    for (int i = 0; i < 3; i++) {
        for (int d = 0; d < 4; d++) {
            float s = 0.f;
            for (int t = lane; t < HH; t += 32)
                s += up_We[(i * 4 + d) * HH + t] * up_ae[i * HH + t];
            s = warpsum(s);
            if (lane == 0) g_pre[i * 4 + d] = s;
        }
    }
    float s = 0.f;
    for (int t = lane; t < HH; t += 32) s += up_W0[t] * as0[t];
    s = warpsum(s);
    if (lane == 0) g_pre[12] = s;
    s = 0.f;
    for (int t = lane; t < HH; t += 32) s += up_W0[t] * ad0[t];
    s = warpsum(s);
    if (lane == 0) g_pre[13] = s;
}

// ---------------- up attention (standalone): warp per node -----------------
__global__ void up_attn_k(const float* __restrict__ h, const float* __restrict__ a_s,
                          const float* __restrict__ a_d,
                          const float* __restrict__ edge_attr, int layer,
                          const float* __restrict__ bias, float* __restrict__ out) {
    int w = threadIdx.x >> 5, lane = threadIdx.x & 31;
    int v = blockIdx.x * 8 + w;
    int l = v & (LL - 1), bi = v >> LOG2L;
    const float4* H = (const float4*)h;
    float4 hv = H[(size_t)v * 32 + lane];
    float4 b4 = ((const float4*)bias)[lane];
    int nc = (l < 1023) ? 2 : ((l == 1023) ? 1 : 0);
    float4* O = (float4*)(out + (size_t)v * HH);
    if (nc == 0) {
        float4 o;
        o.x = fmaxf(hv.x + b4.x, 0.f); o.y = fmaxf(hv.y + b4.y, 0.f);
        o.z = fmaxf(hv.z + b4.z, 0.f); o.w = fmaxf(hv.w + b4.w, 0.f);
        O[lane] = o;
        return;
    }
    int c1 = v + l + 1;
    float4 h1 = H[(size_t)c1 * 32 + lane];
    float4 h2 = (nc == 2) ? H[(size_t)(c1 + 1) * 32 + lane] : make_float4(0, 0, 0, 0);
    float4 as4 = ((const float4*)a_s)[lane];
    float4 ad4 = ((const float4*)a_d)[lane];
    float A1 = warpsum(dot4(h1, as4));
    float A2 = warpsum(dot4(h2, as4));
    float AV = warpsum(dot4(hv, as4));
    float DV = warpsum(dot4(hv, ad4));

    const float* we = g_pre + layer * 4;
    long e1 = (long)bi * 2047 + 2 * l;
    const float* ea1 = edge_attr + e1 * 4;
    float e1s = ea1[0] * we[0] + ea1[1] * we[1] + ea1[2] * we[2] + ea1[3] * we[3];
    float e2s = 0.f;
    if (nc == 2) {
        const float* ea2 = ea1 + 4;
        e2s = ea2[0] * we[0] + ea2[1] * we[1] + ea2[2] * we[2] + ea2[3] * we[3];
    }
    float s1 = lrelu(A1 + DV + e1s);
    float s2 = (nc == 2) ? lrelu(A2 + DV + e2s) : -1e30f;
    float emean = (nc == 2) ? 0.5f * (e1s + e2s) : e1s;
    float ss = lrelu(AV + DV + emean);
    float m = fmaxf(ss, fmaxf(s1, s2));
    float w1 = __expf(s1 - m);
    float w2 = (nc == 2) ? __expf(s2 - m) : 0.f;
    float ws = __expf(ss - m);
    float inv = 1.f / (w1 + w2 + ws);
    float4 o;
    o.x = fmaxf((w1 * h1.x + w2 * h2.x + ws * hv.x) * inv + b4.x, 0.f);
    o.y = fmaxf((w1 * h1.y + w2 * h2.y + ws * hv.y) * inv + b4.y, 0.f);
    o.z = fmaxf((w1 * h1.z + w2 * h2.z + ws * hv.z) * inv + b4.z, 0.f);
    o.w = fmaxf((w1 * h1.w + w2 * h2.w + ws * hv.w) * inv + b4.w, 0.f);
    O[lane] = o;
}

// ------- last down_attn fused with final dot: warp per node ---------------
__global__ void down_final_k(const float* __restrict__ h, const float* __restrict__ bias,
                             const float* __restrict__ x_up, const float* __restrict__ wlast,
                             float* __restrict__ emb, float* __restrict__ dotv) {
    int w = threadIdx.x >> 5, lane = threadIdx.x & 31;
    int v = blockIdx.x * 8 + w;
    int l = v & (LL - 1);
    float4 xu = ((const float4*)x_up)[(size_t)v * 32 + lane];
    float4 b4 = ((const float4*)bias)[lane];
    float4 val;
    if (l == 0) val = b4;
    else {
        int p = v - l + ((l - 1) >> 1);
        float4 hp = ((const float4*)h)[(size_t)p * 32 + lane];
        val.x = hp.x + b4.x; val.y = hp.y + b4.y;
        val.z = hp.z + b4.z; val.w = hp.w + b4.w;
    }
    float4 o;
    o.x = fmaxf(val.x, 0.f) + xu.x;
    o.y = fmaxf(val.y, 0.f) + xu.y;
    o.z = fmaxf(val.z, 0.f) + xu.z;
    o.w = fmaxf(val.w, 0.f) + xu.w;
    ((float4*)(emb + (size_t)v * HH))[lane] = o;
    float4 w4 = ((const float4*)wlast)[lane];
    float q = warpsum(dot4(o, w4));
    if (lane == 0) dotv[v] = q;
}

// ---------------- out[v] = dotv[v] - dotv[root(v)] -------------------------
__global__ void sub_k(const float* __restrict__ dotv, float* __restrict__ out) {
    int v = blockIdx.x * 256 + threadIdx.x;
    out[v] = dotv[v] - dotv[v & ~(LL - 1)];
}

// ---------------------------------------------------------------------------
extern "C" void kernel_launch(void* const* d_in, const int* in_sizes, int n_in,
                              void* d_out, int out_size) {
    const float* x         = (const float*)d_in[0];
    const float* edge_attr = (const float*)d_in[3];
    const float* up_W0     = (const float*)d_in[4];
    const float* up_W      = (const float*)d_in[5];
    const float* up_as     = (const float*)d_in[6];
    const float* up_ad     = (const float*)d_in[7];
    const float* up_We     = (const float*)d_in[8];
    const float* up_ae     = (const float*)d_in[9];
    const float* up_b      = (const float*)d_in[10];
    const float* down_W    = (const float*)d_in[11];
    const float* down_b    = (const float*)d_in[16];
    const float* lin_W     = (const float*)d_in[17];
    const float* lin_b     = (const float*)d_in[18];
    const float* lin_lW    = (const float*)d_in[19];

    float *bufA, *bufB, *bufC, *bufD;
    __nv_bfloat16* wt;
    cudaGetSymbolAddress((void**)&bufA, g_bufA);
    cudaGetSymbolAddress((void**)&bufB, g_bufB);
    cudaGetSymbolAddress((void**)&bufC, g_bufC);
    cudaGetSymbolAddress((void**)&bufD, g_bufD);
    cudaGetSymbolAddress((void**)&wt, g_wt);

    cudaFuncSetAttribute(gemm_hmma, cudaFuncAttributeMaxDynamicSharedMemorySize,
                         SMEM_GEMM);
    cudaFuncSetAttribute(gemm_fused2, cudaFuncAttributeMaxDynamicSharedMemorySize,
                         SMEM_FUSED);

    float* out = (float*)d_out;
    float* emb = out + NN;   // output tuple: (out[B*L], emb[B*L*H]) concatenated

    // mats: 0,1 = up_W[0..1]; 2,3 = down_W[0..1]; 4,5 = lin_W[0..1]
    #define WT(m) (wt + (m) * 2 * 16384)

    precompute_k<<<1, 32>>>(up_We, up_ae, up_W0, up_as, up_ad);
    rank_k<<<1, 128>>>(up_W0, up_b);
    table_k<<<129, 128>>>(up_W0, up_b, up_W);
    wconv_k<<<768, 128>>>(up_W, down_W, lin_W);

    // --- layers 0+1 GEMM collapsed: C1 = relu(comb*W0+b0) @ up_W1 via
    //     piecewise-linear table (exact fp32) ---
    layer1_k<<<NN / 8, 256>>>(x, edge_attr, bufC);
    up_attn_k<<<NN / 8, 256>>>(bufC, up_as + HH, up_ad + HH, edge_attr, 1, up_b + HH, bufB);

    // --- up layer 2 -> x_up (bufA) ---
    gemm_hmma<<<GEMM_GRID, 256, SMEM_GEMM>>>(bufB, WT(1), bufC);
    up_attn_k<<<NN / 8, 256>>>(bufC, up_as + 2 * HH, up_ad + 2 * HH, edge_attr, 2,
                               up_b + 2 * HH, bufA);

    // --- down 0 GEMM: C0 = x_up @ down_W0 ---
    gemm_hmma<<<GEMM_GRID, 256, SMEM_GEMM>>>(bufA, WT(2), bufC);

    // --- loop i=0 fused: bufD = [relu(gather(bufC))+xup] @linW0 relu @downW0
    gemm_fused2<<<FGRID, 512, SMEM_FUSED>>>(bufC, bufA, down_b,
                                            WT(4), lin_b, WT(2), bufD);
    // --- loop i=1 fused: bufC = [relu(gather(bufD))+xup] @linW1 relu @downW1
    gemm_fused2<<<FGRID, 512, SMEM_FUSED>>>(bufD, bufA, down_b,
                                            WT(5), lin_b + HH, WT(3), bufC);

    // --- last down_attn fused with final dot (emb into d_out, dotv in bufB) ---
    down_final_k<<<NN / 8, 256>>>(bufC, down_b + HH, bufA, lin_lW, emb, bufB);

    // --- out[v] = dotv[v] - dotv[root] ---
    sub_k<<<NN / 256, 256>>>(bufB, out);
}

// round 17
// speedup vs baseline: 1.1271x; 1.0081x over previous
#include <cuda_runtime.h>
#include <cuda_bf16.h>
#include <cstdint>

#define NN 131072      // B*L nodes
#define LL 2048        // nodes per tree
#define HH 128         // hidden
#define LOG2L 11
#define GEMM_GRID 296  // 2 CTAs per SM x 148 SMs, persistent
#define NTILES 2048    // NN / 64
#define FTILES 1024    // NN / 128 (fused kernel, 128-row tiles)
#define FGRID 148

// ---------------- scratch (device globals; no allocation allowed) ----------
__device__ float g_bufA[NN * HH];   // x_up
__device__ float g_bufB[NN * HH];   // layer cur
__device__ float g_bufC[NN * HH];   // gemm out
__device__ float g_bufD[NN * HH];   // fused chain ping-pong
__device__ float g_sc[NN * 2];      // per-node (h·a_s, h·a_d) scores
__device__ float g_coef[NN * 4];    // per-node softmax coefs (w1,w2,ws,0)
__device__ float g_pre[16];         // [0..11] w_e per up layer, [12]=W0·a_s, [13]=W0·a_d
__device__ float g_thr[128];        // sorted relu breakpoints for layer0+gemm1
__device__ int   g_ord[128];        // permutation: sorted idx -> original j
__device__ float g_tabU[129 * 128]; // per-interval affine slope table
__device__ float g_tabV[129 * 128]; // per-interval affine offset table
__device__ float g_tabS[129 * 4];   // per-interval score scalars (US,VS,UD,VD)
__device__ __nv_bfloat16 g_wt[12 * 16384];  // 6 mats x {hi,lo} planes, transposed [n][k]

__device__ __forceinline__ float lrelu(float v) { return v > 0.f ? v : 0.2f * v; }
__device__ __forceinline__ float warpsum(float v) {
    #pragma unroll
    for (int o = 16; o; o >>= 1) v += __shfl_xor_sync(0xffffffffu, v, o);
    return v;
}
__device__ __forceinline__ float dot4(float4 a, float4 b) {
    return a.x * b.x + a.y * b.y + a.z * b.z + a.w * b.w;
}
__device__ __forceinline__ uint32_t smem_u32(const void* p) {
    uint32_t a;
    asm("{ .reg .u64 t; cvta.to.shared.u64 t, %1; cvt.u32.u64 %0, t; }" : "=r"(a) : "l"(p));
    return a;
}

// ======================= HMMA helpers (sm_80+ PTX) =========================
__device__ __forceinline__ void ldsm_x4(uint32_t* r, uint32_t addr) {
    asm volatile("ldmatrix.sync.aligned.m8n8.x4.shared.b16 {%0,%1,%2,%3}, [%4];"
                 : "=r"(r[0]), "=r"(r[1]), "=r"(r[2]), "=r"(r[3]) : "r"(addr));
}
__device__ __forceinline__ void mma16816(float* c, const uint32_t* a, const uint32_t* b) {
    asm volatile("mma.sync.aligned.m16n8k16.row.col.f32.bf16.bf16.f32 "
                 "{%0,%1,%2,%3}, {%4,%5,%6,%7}, {%8,%9}, {%0,%1,%2,%3};"
                 : "+f"(c[0]), "+f"(c[1]), "+f"(c[2]), "+f"(c[3])
                 : "r"(a[0]), "r"(a[1]), "r"(a[2]), "r"(a[3]), "r"(b[0]), "r"(b[1]));
}

// SMEM layout, plain GEMM (row stride 272 B)
#define A_HI 0
#define A_LO 17408
#define B_HI 34816
#define B_LO 69632
#define SC_OFF 104448      // 64 rows x 2 floats score scratch
#define SMEM_GEMM 104960
// SMEM layout, fused kernel (128-row A, two B matrices)
#define FA_HI 0
#define FA_LO 34816
#define FB1_HI 69632
#define FB1_LO 104448
#define FB2_HI 139264
#define FB2_LO 174080
#define SMEM_FUSED 208896

// ---------------- weight pre-conversion: W[k][n] -> hi/lo bf16 [n][k] ------
__global__ void wconv_k(const float* __restrict__ up_W,
                        const float* __restrict__ down_W,
                        const float* __restrict__ lin_W) {
    int bx = blockIdx.x;
    int mat = bx >> 7, n = bx & 127, k = threadIdx.x;
    const float* W = (mat < 2) ? up_W + mat * 16384
                   : (mat < 4) ? down_W + (mat - 2) * 16384
                               : lin_W + (mat - 4) * 16384;
    float w = W[k * 128 + n];
    __nv_bfloat16 hb = __float2bfloat16(w);
    float hf = __bfloat162float(hb);
    g_wt[(mat * 2 + 0) * 16384 + n * 128 + k] = hb;
    g_wt[(mat * 2 + 1) * 16384 + n * 128 + k] = __float2bfloat16(w - hf);
}

// ---- rank_k: sort relu breakpoints t_j = -b/W0 (1 small block, smem only) -
__global__ void rank_k(const float* __restrict__ W0, const float* __restrict__ ub) {
    __shared__ float t[128];
    int j = threadIdx.x;
    float w0 = W0[j], b = ub[j];
    float tj = (w0 != 0.f) ? (-b / w0) : 3.0e38f;
    t[j] = tj;
    __syncthreads();
    int rank = 0;
    for (int k = 0; k < 128; k++) {
        float tk = t[k];
        if (tk < tj || (tk == tj && k < j)) rank++;
    }
    g_thr[rank] = tj;
    g_ord[rank] = j;
}

// ---- table_k: interval i row of (U,V); 129 blocks x 128 threads (parallel)
__global__ void table_k(const float* __restrict__ W0, const float* __restrict__ ub,
                        const float* __restrict__ W1) {
    __shared__ float w0s[128], bs[128];
    __shared__ int ords[128];
    int n = threadIdx.x, i = blockIdx.x;
    w0s[n] = W0[n]; bs[n] = ub[n]; ords[n] = g_ord[n];
    __syncthreads();
    float U = 0.f, V = 0.f;
    #pragma unroll 4
    for (int m = 0; m < 128; m++) {
        int j = ords[m];
        float w0 = w0s[j], b = bs[j];
        float w1 = W1[j * 128 + n];
        bool act = (w0 > 0.f && m < i) || (w0 < 0.f && m >= i) ||
                   (w0 == 0.f && b > 0.f);
        if (act) { U += w0 * w1; V += b * w1; }
    }
    g_tabU[i * 128 + n] = U;
    g_tabV[i * 128 + n] = V;
}

// ---- tabdot_k: per-interval score scalars (tabU·a_s, tabV·a_s, ·a_d) ------
__global__ void tabdot_k(const float* __restrict__ avs, const float* __restrict__ avd) {
    int i = blockIdx.x, lane = threadIdx.x;   // 129 blocks x 32
    float us = 0.f, vs = 0.f, ud = 0.f, vd = 0.f;
    #pragma unroll
    for (int q = 0; q < 4; q++) {
        int k = lane + q * 32;
        float u = g_tabU[i * 128 + k], v = g_tabV[i * 128 + k];
        float as = avs[k], ad = avd[k];
        us += u * as; vs += v * as; ud += u * ad; vd += v * ad;
    }
    us = warpsum(us); vs = warpsum(vs); ud = warpsum(ud); vd = warpsum(vd);
    if (lane == 0) {
        g_tabS[i * 4 + 0] = us; g_tabS[i * 4 + 1] = vs;
        g_tabS[i * 4 + 2] = ud; g_tabS[i * 4 + 3] = vd;
    }
}

// ---- layer1_k: C1[v,:] = comb(v)*U_i + V_i, plus layer-1 attn scores ------
__global__ void layer1_k(const float* __restrict__ x,
                         const float* __restrict__ edge_attr,
                         float* __restrict__ out, float* __restrict__ sc) {
    int w = threadIdx.x >> 5, lane = threadIdx.x & 31;
    int v = blockIdx.x * 8 + w;
    int l = v & (LL - 1), bi = v >> LOG2L;
    float xv = x[v];
    int nc = (l < 1023) ? 2 : ((l == 1023) ? 1 : 0);
    float comb;
    if (nc == 0) {
        comb = xv;
    } else {
        float was = g_pre[12], wad = g_pre[13];
        int c1 = v + l + 1;
        float x1 = x[c1];
        float x2 = (nc == 2) ? x[c1 + 1] : 0.f;
        long e1 = (long)bi * 2047 + 2 * l;
        const float* ea1 = edge_attr + e1 * 4;
        float e1s = ea1[0] * g_pre[0] + ea1[1] * g_pre[1] +
                    ea1[2] * g_pre[2] + ea1[3] * g_pre[3];
        float e2s = 0.f;
        if (nc == 2) {
            const float* ea2 = ea1 + 4;
            e2s = ea2[0] * g_pre[0] + ea2[1] * g_pre[1] +
                  ea2[2] * g_pre[2] + ea2[3] * g_pre[3];
        }
        float adv = xv * wad;
        float s1 = lrelu(x1 * was + adv + e1s);
        float s2 = (nc == 2) ? lrelu(x2 * was + adv + e2s) : -1e30f;
        float emean = (nc == 2) ? 0.5f * (e1s + e2s) : e1s;
        float ss = lrelu(xv * was + adv + emean);
        float m = fmaxf(ss, fmaxf(s1, s2));
        float w1 = __expf(s1 - m);
        float w2 = (nc == 2) ? __expf(s2 - m) : 0.f;
        float ws = __expf(ss - m);
        comb = (w1 * x1 + w2 * x2 + ws * xv) / (w1 + w2 + ws);
    }
    float cnt = (g_thr[lane] < comb ? 1.f : 0.f) +
                (g_thr[lane + 32] < comb ? 1.f : 0.f) +
                (g_thr[lane + 64] < comb ? 1.f : 0.f) +
                (g_thr[lane + 96] < comb ? 1.f : 0.f);
    int i = (int)warpsum(cnt);
    const float4* U4 = (const float4*)(g_tabU + i * 128);
    const float4* V4 = (const float4*)(g_tabV + i * 128);
    float4 u = U4[lane], vv = V4[lane];
    float4 o;
    o.x = comb * u.x + vv.x;
    o.y = comb * u.y + vv.y;
    o.z = comb * u.z + vv.z;
    o.w = comb * u.w + vv.w;
    ((float4*)(out + (size_t)v * HH))[lane] = o;
    if (lane == 0) {
        sc[v * 2 + 0] = comb * g_tabS[i * 4 + 0] + g_tabS[i * 4 + 1];
        sc[v * 2 + 1] = comb * g_tabS[i * 4 + 2] + g_tabS[i * 4 + 3];
    }
}

// ---- coef_k: per-node softmax coefs from scores + edge dots (high occ) ----
__global__ void coef_k(const float* __restrict__ sc, const float* __restrict__ edge_attr,
                       int layer, float4* __restrict__ coef) {
    int v = blockIdx.x * 256 + threadIdx.x;
    int l = v & (LL - 1), bi = v >> LOG2L;
    int nc = (l < 1023) ? 2 : ((l == 1023) ? 1 : 0);
    if (nc == 0) { coef[v] = make_float4(0.f, 0.f, 1.f, 0.f); return; }
    float svx = sc[v * 2 + 0], svy = sc[v * 2 + 1];
    int c1 = v + l + 1;
    float s1src = sc[(size_t)c1 * 2];
    float s2src = (nc == 2) ? sc[(size_t)(c1 + 1) * 2] : 0.f;
    const float* we = g_pre + layer * 4;
    long e1 = (long)bi * 2047 + 2 * l;
    const float* ea1 = edge_attr + e1 * 4;
    float e1s = ea1[0] * we[0] + ea1[1] * we[1] + ea1[2] * we[2] + ea1[3] * we[3];
    float e2s = 0.f;
    if (nc == 2) {
        const float* ea2 = ea1 + 4;
        e2s = ea2[0] * we[0] + ea2[1] * we[1] + ea2[2] * we[2] + ea2[3] * we[3];
    }
    float s1 = lrelu(s1src + svy + e1s);
    float s2 = (nc == 2) ? lrelu(s2src + svy + e2s) : -1e30f;
    float emean = (nc == 2) ? 0.5f * (e1s + e2s) : e1s;
    float ss = lrelu(svx + svy + emean);
    float m = fmaxf(ss, fmaxf(s1, s2));
    float w1 = __expf(s1 - m);
    float w2 = (nc == 2) ? __expf(s2 - m) : 0.f;
    float ws = __expf(ss - m);
    float inv = 1.f / (w1 + w2 + ws);
    coef[v] = make_float4(w1 * inv, w2 * inv, ws * inv, 0.f);
}

// ---- up_combine_k: out[v] = relu(cf.x*h[c1]+cf.y*h[c2]+cf.z*h[v]+b) -------
// Pure gather + FMA, no reductions/expf: high-occupancy, flat float4.
__global__ void up_combine_k(const float* __restrict__ h, const float4* __restrict__ coef,
                             const float* __restrict__ bias, float* __restrict__ out) {
    int i = blockIdx.x * 256 + threadIdx.x;   // over NN*32 float4s
    int v = i >> 5, q = i & 31;
    int l = v & (LL - 1);
    float4 cf = coef[v];
    int c1 = (l <= 1023) ? v + l + 1 : v;
    int c2 = (l <= 1022) ? v + l + 2 : v;
    const float4* H = (const float4*)h;
    float4 h1 = H[(size_t)c1 * 32 + q];
    float4 h2 = H[(size_t)c2 * 32 + q];
    float4 hv = H[(size_t)v * 32 + q];
    float4 b4 = ((const float4*)bias)[q];
    float4 o;
    o.x = fmaxf(cf.x * h1.x + cf.y * h2.x + cf.z * hv.x + b4.x, 0.f);
    o.y = fmaxf(cf.x * h1.y + cf.y * h2.y + cf.z * hv.y + b4.y, 0.f);
    o.z = fmaxf(cf.x * h1.z + cf.y * h2.z + cf.z * hv.z + b4.z, 0.f);
    o.w = fmaxf(cf.x * h1.w + cf.y * h2.w + cf.z * hv.w + b4.w, 0.f);
    ((float4*)out)[i] = o;
}

// ============== persistent HMMA GEMM: C = A @ W (+optional score epilogue) =
__global__ void __launch_bounds__(256, 2)
gemm_hmma(const float* __restrict__ A,
          const float* __restrict__ avs, const float* __restrict__ avd,
          float* __restrict__ sc_out,
          const __nv_bfloat16* __restrict__ Wt, float* __restrict__ C) {
    extern __shared__ char smem[];
    uint32_t sb = smem_u32(smem);
    int tid = threadIdx.x;

    const uint4* Bh = (const uint4*)Wt;
    const uint4* Bl = (const uint4*)(Wt + 16384);
    #pragma unroll
    for (int i = tid; i < 2048; i += 256) {
        int n = i >> 4, kq = i & 15;
        uint32_t off = n * 272 + kq * 16;
        *(uint4*)(smem + B_HI + off) = Bh[i];
        *(uint4*)(smem + B_LO + off) = Bl[i];
    }

    int wid = tid >> 5, lane = tid & 31;
    int m0 = (wid & 1) * 32, n0 = (wid >> 1) * 32;
    int g = lane >> 3, r = lane & 7;
    uint32_t aoff0 = (uint32_t)((m0 + (g & 1) * 8 + r) * 272 + (g >> 1) * 16);
    uint32_t boff0 = (uint32_t)((n0 + (g >> 1) * 8 + r) * 272 + (g & 1) * 16);
    int cr = lane >> 2, cc = (lane & 3) * 2;

    float as_r[4][2], ad_r[4][2];
    if (sc_out) {
        #pragma unroll
        for (int nf = 0; nf < 4; nf++) {
            int col = n0 + nf * 8 + cc;
            as_r[nf][0] = avs[col]; as_r[nf][1] = avs[col + 1];
            ad_r[nf][0] = avd[col]; ad_r[nf][1] = avd[col + 1];
        }
    }

    for (int tile = blockIdx.x; tile < NTILES; tile += GEMM_GRID) {
        if (sc_out && tid < 128)
            *(float*)(smem + SC_OFF + tid * 4) = 0.f;
        #pragma unroll
        for (int i = tid; i < 2048; i += 256) {
            int row = i >> 5, c4 = i & 31;
            float4 v = ((const float4*)(A + (size_t)tile * 64 * 128))[i];
            float f[4] = {v.x, v.y, v.z, v.w};
            union { uint2 u; __nv_bfloat16 h[4]; } ph, pl;
            #pragma unroll
            for (int e = 0; e < 4; e++) {
                __nv_bfloat16 hb = __float2bfloat16(f[e]);
                ph.h[e] = hb;
                pl.h[e] = __float2bfloat16(f[e] - __bfloat162float(hb));
            }
            uint32_t off = row * 272 + c4 * 8;
            *(uint2*)(smem + A_HI + off) = ph.u;
            *(uint2*)(smem + A_LO + off) = pl.u;
        }
        __syncthreads();

        float acc[2][4][4];
        #pragma unroll
        for (int a = 0; a < 2; a++)
            #pragma unroll
            for (int b = 0; b < 4; b++)
                #pragma unroll
                for (int c = 0; c < 4; c++) acc[a][b][c] = 0.f;

        #pragma unroll 4
        for (int k16 = 0; k16 < 8; k16++) {
            uint32_t ah[2][4], al[2][4], bh[4][2];
            ldsm_x4(ah[0], sb + A_HI + aoff0 + k16 * 32);
            ldsm_x4(ah[1], sb + A_HI + aoff0 + 16 * 272 + k16 * 32);
            ldsm_x4(al[0], sb + A_LO + aoff0 + k16 * 32);
            ldsm_x4(al[1], sb + A_LO + aoff0 + 16 * 272 + k16 * 32);
            ldsm_x4(&bh[0][0], sb + B_HI + boff0 + k16 * 32);
            ldsm_x4(&bh[2][0], sb + B_HI + boff0 + 16 * 272 + k16 * 32);
            #pragma unroll
            for (int mf = 0; mf < 2; mf++)
                #pragma unroll
                for (int nf = 0; nf < 4; nf++)
                    mma16816(acc[mf][nf], ah[mf], bh[nf]);
            #pragma unroll
            for (int mf = 0; mf < 2; mf++)
                #pragma unroll
                for (int nf = 0; nf < 4; nf++)
                    mma16816(acc[mf][nf], al[mf], bh[nf]);
        }
        #pragma unroll 4
        for (int k16 = 0; k16 < 8; k16++) {
            uint32_t ah[2][4], bl[4][2];
            ldsm_x4(ah[0], sb + A_HI + aoff0 + k16 * 32);
            ldsm_x4(ah[1], sb + A_HI + aoff0 + 16 * 272 + k16 * 32);
            ldsm_x4(&bl[0][0], sb + B_LO + boff0 + k16 * 32);
            ldsm_x4(&bl[2][0], sb + B_LO + boff0 + 16 * 272 + k16 * 32);
            #pragma unroll
            for (int mf = 0; mf < 2; mf++)
                #pragma unroll
                for (int nf = 0; nf < 4; nf++)
                    mma16816(acc[mf][nf], ah[mf], bl[nf]);
        }

        size_t rbase = (size_t)tile * 64;
        #pragma unroll
        for (int mf = 0; mf < 2; mf++) {
            #pragma unroll
            for (int nf = 0; nf < 4; nf++) {
                int col = n0 + nf * 8 + cc;
                int row0 = m0 + mf * 16 + cr;
                *(float2*)(C + (rbase + row0) * 128 + col) =
                    make_float2(acc[mf][nf][0], acc[mf][nf][1]);
                *(float2*)(C + (rbase + row0 + 8) * 128 + col) =
                    make_float2(acc[mf][nf][2], acc[mf][nf][3]);
            }
        }

        if (sc_out) {
            #pragma unroll
            for (int mf = 0; mf < 2; mf++) {
                #pragma unroll
                for (int j = 0; j < 2; j++) {
                    int rrow = m0 + mf * 16 + cr + j * 8;
                    float ps = 0.f, pd = 0.f;
                    #pragma unroll
                    for (int nf = 0; nf < 4; nf++) {
                        float a0 = acc[mf][nf][2 * j + 0];
                        float a1 = acc[mf][nf][2 * j + 1];
                        ps += a0 * as_r[nf][0] + a1 * as_r[nf][1];
                        pd += a0 * ad_r[nf][0] + a1 * ad_r[nf][1];
                    }
                    ps += __shfl_xor_sync(0xffffffffu, ps, 1);
                    ps += __shfl_xor_sync(0xffffffffu, ps, 2);
                    pd += __shfl_xor_sync(0xffffffffu, pd, 1);
                    pd += __shfl_xor_sync(0xffffffffu, pd, 2);
                    if ((lane & 3) == 0) {
                        atomicAdd((float*)(smem + SC_OFF + (rrow * 2 + 0) * 4), ps);
                        atomicAdd((float*)(smem + SC_OFF + (rrow * 2 + 1) * 4), pd);
                    }
                }
            }
            __syncthreads();
            if (tid < 128)
                sc_out[(rbase + (tid >> 1)) * 2 + (tid & 1)] =
                    *(float*)(smem + SC_OFF + tid * 4);
        }
        __syncthreads();
    }
}

// ====== fused lin+down chain (unchanged) ===================================
__global__ void __launch_bounds__(512, 1)
gemm_fused2(const float* __restrict__ gC, const float* __restrict__ xup,
            const float* __restrict__ dbias,
            const __nv_bfloat16* __restrict__ Wt1, const float* __restrict__ lbias,
            const __nv_bfloat16* __restrict__ Wt2,
            float* __restrict__ out) {
    extern __shared__ char smem[];
    uint32_t sb = smem_u32(smem);
    int tid = threadIdx.x;

    {
        const uint4* B1h = (const uint4*)Wt1;
        const uint4* B1l = (const uint4*)(Wt1 + 16384);
        const uint4* B2h = (const uint4*)Wt2;
        const uint4* B2l = (const uint4*)(Wt2 + 16384);
        #pragma unroll
        for (int i = tid; i < 2048; i += 512) {
            int n = i >> 4, kq = i & 15;
            uint32_t off = n * 272 + kq * 16;
            *(uint4*)(smem + FB1_HI + off) = B1h[i];
            *(uint4*)(smem + FB1_LO + off) = B1l[i];
            *(uint4*)(smem + FB2_HI + off) = B2h[i];
            *(uint4*)(smem + FB2_LO + off) = B2l[i];
        }
    }

    int wid = tid >> 5, lane = tid & 31;
    int m0 = (wid & 3) * 32, n0 = (wid >> 2) * 32;
    int g = lane >> 3, r = lane & 7;
    uint32_t aoff0 = (uint32_t)((m0 + (g & 1) * 8 + r) * 272 + (g >> 1) * 16);
    uint32_t boff0 = (uint32_t)((n0 + (g >> 1) * 8 + r) * 272 + (g & 1) * 16);
    int cr = lane >> 2, cc = (lane & 3) * 2;

    for (int tile = blockIdx.x; tile < FTILES; tile += FGRID) {
        #pragma unroll
        for (int i = tid; i < 4096; i += 512) {
            int row = i >> 5, c4 = i & 31;
            int vv = tile * 128 + row;
            int l = vv & (LL - 1);
            float4 b4 = ((const float4*)dbias)[c4];
            float4 xu = ((const float4*)xup)[(size_t)vv * 32 + c4];
            float4 v;
            if (l == 0) {
                v.x = fmaxf(b4.x, 0.f) + xu.x;
                v.y = fmaxf(b4.y, 0.f) + xu.y;
                v.z = fmaxf(b4.z, 0.f) + xu.z;
                v.w = fmaxf(b4.w, 0.f) + xu.w;
            } else {
                int p = vv - l + ((l - 1) >> 1);
                float4 cp = ((const float4*)gC)[(size_t)p * 32 + c4];
                v.x = fmaxf(cp.x + b4.x, 0.f) + xu.x;
                v.y = fmaxf(cp.y + b4.y, 0.f) + xu.y;
                v.z = fmaxf(cp.z + b4.z, 0.f) + xu.z;
                v.w = fmaxf(cp.w + b4.w, 0.f) + xu.w;
            }
            float f[4] = {v.x, v.y, v.z, v.w};
            union { uint2 u; __nv_bfloat16 h[4]; } ph, pl;
            #pragma unroll
            for (int e = 0; e < 4; e++) {
                __nv_bfloat16 hb = __float2bfloat16(f[e]);
                ph.h[e] = hb;
                pl.h[e] = __float2bfloat16(f[e] - __bfloat162float(hb));
            }
            uint32_t off = row * 272 + c4 * 8;
            *(uint2*)(smem + FA_HI + off) = ph.u;
            *(uint2*)(smem + FA_LO + off) = pl.u;
        }
        __syncthreads();

        float acc[2][4][4];
        #pragma unroll
        for (int a = 0; a < 2; a++)
            #pragma unroll
            for (int b = 0; b < 4; b++)
                #pragma unroll
                for (int c = 0; c < 4; c++) acc[a][b][c] = 0.f;

        #pragma unroll 4
        for (int k16 = 0; k16 < 8; k16++) {
            uint32_t ah[2][4], al[2][4], bh[4][2];
            ldsm_x4(ah[0], sb + FA_HI + aoff0 + k16 * 32);
            ldsm_x4(ah[1], sb + FA_HI + aoff0 + 16 * 272 + k16 * 32);
            ldsm_x4(al[0], sb + FA_LO + aoff0 + k16 * 32);
            ldsm_x4(al[1], sb + FA_LO + aoff0 + 16 * 272 + k16 * 32);
            ldsm_x4(&bh[0][0], sb + FB1_HI + boff0 + k16 * 32);
            ldsm_x4(&bh[2][0], sb + FB1_HI + boff0 + 16 * 272 + k16 * 32);
            #pragma unroll
            for (int mf = 0; mf < 2; mf++)
                #pragma unroll
                for (int nf = 0; nf < 4; nf++)
                    mma16816(acc[mf][nf], ah[mf], bh[nf]);
            #pragma unroll
            for (int mf = 0; mf < 2; mf++)
                #pragma unroll
                for (int nf = 0; nf < 4; nf++)
                    mma16816(acc[mf][nf], al[mf], bh[nf]);
        }
        #pragma unroll 4
        for (int k16 = 0; k16 < 8; k16++) {
            uint32_t ah[2][4], bl[4][2];
            ldsm_x4(ah[0], sb + FA_HI + aoff0 + k16 * 32);
            ldsm_x4(ah[1], sb + FA_HI + aoff0 + 16 * 272 + k16 * 32);
            ldsm_x4(&bl[0][0], sb + FB1_LO + boff0 + k16 * 32);
            ldsm_x4(&bl[2][0], sb + FB1_LO + boff0 + 16 * 272 + k16 * 32);
            #pragma unroll
            for (int mf = 0; mf < 2; mf++)
                #pragma unroll
                for (int nf = 0; nf < 4; nf++)
                    mma16816(acc[mf][nf], ah[mf], bl[nf]);
        }
        __syncthreads();

        #pragma unroll
        for (int mf = 0; mf < 2; mf++) {
            #pragma unroll
            for (int nf = 0; nf < 4; nf++) {
                int col = n0 + nf * 8 + cc;
                float bx = lbias[col], by = lbias[col + 1];
                #pragma unroll
                for (int j = 0; j < 2; j++) {
                    int row = m0 + mf * 16 + cr + j * 8;
                    float f0 = fmaxf(acc[mf][nf][2 * j + 0] + bx, 0.f);
                    float f1 = fmaxf(acc[mf][nf][2 * j + 1] + by, 0.f);
                    union { uint32_t u; __nv_bfloat16 h[2]; } uh, ul;
                    uh.h[0] = __float2bfloat16(f0);
                    uh.h[1] = __float2bfloat16(f1);
                    ul.h[0] = __float2bfloat16(f0 - __bfloat162float(uh.h[0]));
                    ul.h[1] = __float2bfloat16(f1 - __bfloat162float(uh.h[1]));
                    uint32_t off = row * 272 + col * 2;
                    *(uint32_t*)(smem + FA_HI + off) = uh.u;
                    *(uint32_t*)(smem + FA_LO + off) = ul.u;
                }
            }
        }
        __syncthreads();

        #pragma unroll
        for (int a = 0; a < 2; a++)
            #pragma unroll
            for (int b = 0; b < 4; b++)
                #pragma unroll
                for (int c = 0; c < 4; c++) acc[a][b][c] = 0.f;

        #pragma unroll 4
        for (int k16 = 0; k16 < 8; k16++) {
            uint32_t ah[2][4], al[2][4], bh[4][2];
            ldsm_x4(ah[0], sb + FA_HI + aoff0 + k16 * 32);
            ldsm_x4(ah[1], sb + FA_HI + aoff0 + 16 * 272 + k16 * 32);
            ldsm_x4(al[0], sb + FA_LO + aoff0 + k16 * 32);
            ldsm_x4(al[1], sb + FA_LO + aoff0 + 16 * 272 + k16 * 32);
            ldsm_x4(&bh[0][0], sb + FB2_HI + boff0 + k16 * 32);
            ldsm_x4(&bh[2][0], sb + FB2_HI + boff0 + 16 * 272 + k16 * 32);
            #pragma unroll
            for (int mf = 0; mf < 2; mf++)
                #pragma unroll
                for (int nf = 0; nf < 4; nf++)
                    mma16816(acc[mf][nf], ah[mf], bh[nf]);
            #pragma unroll
            for (int mf = 0; mf < 2; mf++)
                #pragma unroll
                for (int nf = 0; nf < 4; nf++)
                    mma16816(acc[mf][nf], al[mf], bh[nf]);
        }
        #pragma unroll 4
        for (int k16 = 0; k16 < 8; k16++) {
            uint32_t ah[2][4], bl[4][2];
            ldsm_x4(ah[0], sb + FA_HI + aoff0 + k16 * 32);
            ldsm_x4(ah[1], sb + FA_HI + aoff0 + 16 * 272 + k16 * 32);
            ldsm_x4(&bl[0][0], sb + FB2_LO + boff0 + k16 * 32);
            ldsm_x4(&bl[2][0], sb + FB2_LO + boff0 + 16 * 272 + k16 * 32);
            #pragma unroll
            for (int mf = 0; mf < 2; mf++)
                #pragma unroll
                for (int nf = 0; nf < 4; nf++)
                    mma16816(acc[mf][nf], ah[mf], bl[nf]);
        }

        size_t rbase = (size_t)tile * 128;
        #pragma unroll
        for (int mf = 0; mf < 2; mf++) {
            #pragma unroll
            for (int nf = 0; nf < 4; nf++) {
                int col = n0 + nf * 8 + cc;
                int row0 = m0 + mf * 16 + cr;
                *(float2*)(out + (rbase + row0) * 128 + col) =
                    make_float2(acc[mf][nf][0], acc[mf][nf][1]);
                *(float2*)(out + (rbase + row0 + 8) * 128 + col) =
                    make_float2(acc[mf][nf][2], acc[mf][nf][3]);
            }
        }
        __syncthreads();
    }
}

// ---------------- tiny precompute: w_e = We @ a_e per up layer, W0 dots ----
__global__ void precompute_k(const float* __restrict__ up_We,
                             const float* __restrict__ up_ae,
                             const float* __restrict__ up_W0,
                             const float* __restrict__ as0,
                             const float* __restrict__ ad0) {
    int lane = threadIdx.x;
    for (int i = 0; i < 3; i++) {
        for (int d = 0; d < 4; d++) {
            float s = 0.f;
            for (int t = lane; t < HH; t += 32)
                s += up_We[(i * 4 + d) * HH + t] * up_ae[i * HH + t];
            s = warpsum(s);
            if (lane == 0) g_pre[i * 4 + d] = s;
        }
    }
    float s = 0.f;
    for (int t = lane; t < HH; t += 32) s += up_W0[t] * as0[t];
    s = warpsum(s);
    if (lane == 0) g_pre[12] = s;
    s = 0.f;
    for (int t = lane; t < HH; t += 32) s += up_W0[t] * ad0[t];
    s = warpsum(s);
    if (lane == 0) g_pre[13] = s;
}

// ------- last down_attn fused with final dot AND root-sub ------------------
__global__ void down_final_k(const float* __restrict__ h, const float* __restrict__ bias,
                             const float* __restrict__ x_up, const float* __restrict__ wlast,
                             float* __restrict__ emb, float* __restrict__ outv) {
    int w = threadIdx.x >> 5, lane = threadIdx.x & 31;
    int v = blockIdx.x * 8 + w;
    int l = v & (LL - 1);
    float4 xu = ((const float4*)x_up)[(size_t)v * 32 + lane];
    float4 b4 = ((const float4*)bias)[lane];
    float4 val;
    if (l == 0) val = b4;
    else {
        int p = v - l + ((l - 1) >> 1);
        float4 hp = ((const float4*)h)[(size_t)p * 32 + lane];
        val.x = hp.x + b4.x; val.y = hp.y + b4.y;
        val.z = hp.z + b4.z; val.w = hp.w + b4.w;
    }
    float4 o;
    o.x = fmaxf(val.x, 0.f) + xu.x;
    o.y = fmaxf(val.y, 0.f) + xu.y;
    o.z = fmaxf(val.z, 0.f) + xu.z;
    o.w = fmaxf(val.w, 0.f) + xu.w;
    ((float4*)(emb + (size_t)v * HH))[lane] = o;
    // root emb is cheap to recompute (l==0 path): relu(b)+x_up[root]
    float4 xr = ((const float4*)x_up)[(size_t)(v - l) * 32 + lane];
    float4 orr;
    orr.x = fmaxf(b4.x, 0.f) + xr.x;
    orr.y = fmaxf(b4.y, 0.f) + xr.y;
    orr.z = fmaxf(b4.z, 0.f) + xr.z;
    orr.w = fmaxf(b4.w, 0.f) + xr.w;
    float4 w4 = ((const float4*)wlast)[lane];
    float q = warpsum(dot4(o, w4) - dot4(orr, w4));
    if (lane == 0) outv[v] = q;
}

// ---------------------------------------------------------------------------
extern "C" void kernel_launch(void* const* d_in, const int* in_sizes, int n_in,
                              void* d_out, int out_size) {
    const float* x         = (const float*)d_in[0];
    const float* edge_attr = (const float*)d_in[3];
    const float* up_W0     = (const float*)d_in[4];
    const float* up_W      = (const float*)d_in[5];
    const float* up_as     = (const float*)d_in[6];
    const float* up_ad     = (const float*)d_in[7];
    const float* up_We     = (const float*)d_in[8];
    const float* up_ae     = (const float*)d_in[9];
    const float* up_b      = (const float*)d_in[10];
    const float* down_W    = (const float*)d_in[11];
    const float* down_b    = (const float*)d_in[16];
    const float* lin_W     = (const float*)d_in[17];
    const float* lin_b     = (const float*)d_in[18];
    const float* lin_lW    = (const float*)d_in[19];

    float *bufA, *bufB, *bufC, *bufD, *sc, *coef;
    __nv_bfloat16* wt;
    cudaGetSymbolAddress((void**)&bufA, g_bufA);
    cudaGetSymbolAddress((void**)&bufB, g_bufB);
    cudaGetSymbolAddress((void**)&bufC, g_bufC);
    cudaGetSymbolAddress((void**)&bufD, g_bufD);
    cudaGetSymbolAddress((void**)&sc, g_sc);
    cudaGetSymbolAddress((void**)&coef, g_coef);
    cudaGetSymbolAddress((void**)&wt, g_wt);

    cudaFuncSetAttribute(gemm_hmma, cudaFuncAttributeMaxDynamicSharedMemorySize,
                         SMEM_GEMM);
    cudaFuncSetAttribute(gemm_fused2, cudaFuncAttributeMaxDynamicSharedMemorySize,
                         SMEM_FUSED);

    float* out = (float*)d_out;
    float* emb = out + NN;   // output tuple: (out[B*L], emb[B*L*H]) concatenated

    // mats: 0,1 = up_W[0..1]; 2,3 = down_W[0..1]; 4,5 = lin_W[0..1]
    #define WT(m) (wt + (m) * 2 * 16384)

    precompute_k<<<1, 32>>>(up_We, up_ae, up_W0, up_as, up_ad);
    rank_k<<<1, 128>>>(up_W0, up_b);
    table_k<<<129, 128>>>(up_W0, up_b, up_W);
    tabdot_k<<<129, 32>>>(up_as + HH, up_ad + HH);
    wconv_k<<<768, 128>>>(up_W, down_W, lin_W);

    // --- layers 0+1 collapsed (exact) + layer-1 scores ---
    layer1_k<<<NN / 8, 256>>>(x, edge_attr, bufC, sc);
    coef_k<<<NN / 256, 256>>>(sc, edge_attr, 1, (float4*)coef);
    up_combine_k<<<NN * 32 / 256, 256>>>(bufC, (const float4*)coef, up_b + HH, bufB);

    // --- up layer 2 GEMM with layer-2 score epilogue ---
    gemm_hmma<<<GEMM_GRID, 256, SMEM_GEMM>>>(bufB, up_as + 2 * HH, up_ad + 2 * HH,
                                             sc, WT(1), bufC);
    coef_k<<<NN / 256, 256>>>(sc, edge_attr, 2, (float4*)coef);
    up_combine_k<<<NN * 32 / 256, 256>>>(bufC, (const float4*)coef, up_b + 2 * HH, bufA);

    // --- down 0 GEMM: C0 = x_up @ down_W0 ---
    gemm_hmma<<<GEMM_GRID, 256, SMEM_GEMM>>>(bufA, nullptr, nullptr, nullptr,
                                             WT(2), bufC);

    // --- loop i=0 fused: bufD = [relu(gather(bufC))+xup] @linW0 relu @downW0
    gemm_fused2<<<FGRID, 512, SMEM_FUSED>>>(bufC, bufA, down_b,
                                            WT(4), lin_b, WT(2), bufD);
    // --- loop i=1 fused: bufC = [relu(gather(bufD))+xup] @linW1 relu @downW1
    gemm_fused2<<<FGRID, 512, SMEM_FUSED>>>(bufD, bufA, down_b,
                                            WT(5), lin_b + HH, WT(3), bufC);

    // --- last down_attn + final dot + root-sub (emb into d_out) ---
    down_final_k<<<NN / 8, 256>>>(bufC, down_b + HH, bufA, lin_lW, emb, out);
}